// round 11
// baseline (speedup 1.0000x reference)
#include <cuda_runtime.h>
#include <cuda_fp16.h>
#include <math.h>

#define N_NODES 100000
#define N_EDGES 20000
#define NNZ     1600000
#define D       128
#define NB_V    ((N_NODES + 1023) / 1024)   // 98
#define NB_E    ((N_EDGES + 1023) / 1024)   // 20

// ---------------- scratch (device globals: allocation-free rule) ----------------
// Invariant: g_cnt_v/g_cnt_e/g_state_v/g_state_e are ZERO at entry (statically
// zero-initialized; re-zeroed by fill_kernel after last use each execution).
__device__ int   g_cnt_v[N_NODES];
__device__ int   g_cnt_e[N_EDGES];
__device__ unsigned long long g_state_v[NB_V];    // lookback: (value<<2)|flag
__device__ unsigned long long g_state_e[NB_E];
__device__ int   g_offs_v[N_NODES + 1];
__device__ int   g_offs_e[N_EDGES + 1];
__device__ int   g_pos[NNZ];                      // (pos_v << 16) | pos_e
__device__ float g_inv_sqrt_dv[N_NODES];
__device__ float g_inv_de[N_EDGES];
__device__ int   g_edge_adj[NNZ];                 // per-edge list of vertex ids
__device__ unsigned short g_node_adj[NNZ];        // per-node list of edge ids (<2^16)
__device__ unsigned g_Xh[(size_t)N_NODES * 64];   // X in half2 bit patterns
__device__ float g_Yp[(size_t)N_EDGES * D];       // inv_de * H^T Dv^-1/2 X (fp32)
__device__ float g_se[N_EDGES];                   // inv_de * H^T Dv^-1/2 1
__device__ unsigned g_Yeh[(size_t)N_EDGES * 64];  // Ye in half2

// ---------------- 1: degree histograms + rank capture + X->half2 convert ----------------
__global__ void degree_convert_kernel(const float* __restrict__ X,
                                      const int* __restrict__ v_idx,
                                      const int* __restrict__ e_idx) {
    cudaTriggerProgrammaticLaunchCompletion();       // let scan launch early
    int i = blockIdx.x * blockDim.x + threadIdx.x;   // grid covers N_NODES*32
    if (i < N_NODES * 32) {
        float4 p = __ldcs(((const float4*)X) + i);   // evict-first: X is read once
        __half2 a = __floats2half2_rn(p.x, p.y);
        __half2 b = __floats2half2_rn(p.z, p.w);
        uint2 r;
        r.x = *reinterpret_cast<const unsigned*>(&a);
        r.y = *reinterpret_cast<const unsigned*>(&b);
        ((uint2*)g_Xh)[i] = r;
    }
    if (i < NNZ) {
        int pv = atomicAdd(&g_cnt_v[v_idx[i]], 1);
        int pe = atomicAdd(&g_cnt_e[e_idx[i]], 1);
        g_pos[i] = (pv << 16) | pe;
    }
}

// ---------------- 2: single-pass decoupled-lookback scan (both arrays) + inv factors ----------------
__global__ void scan_fused_kernel() {
    __shared__ int wsum[32];
    __shared__ int s_agg;
    __shared__ int s_prefix;
    int tid = threadIdx.x;                        // 1024
    int b = blockIdx.x;
    cudaTriggerProgrammaticLaunchCompletion();    // let fill launch early
    int chain_e = (b >= NB_V);
    int pb = chain_e ? (b - NB_V) : b;
    const int* in   = chain_e ? g_cnt_e : g_cnt_v;
    int*       out  = chain_e ? g_offs_e : g_offs_v;
    int        n    = chain_e ? N_EDGES : N_NODES;
    unsigned long long* st = chain_e ? g_state_e : g_state_v;

    int i = pb * 1024 + tid;

    cudaGridDependencySynchronize();              // wait for degree counts

    int x = (i < n) ? in[i] : 0;

    if (i < n) {
        if (chain_e) g_inv_de[i] = (x > 0) ? (1.0f / (float)x) : 0.0f;
        else         g_inv_sqrt_dv[i] = (x > 0) ? rsqrtf((float)x) : 0.0f;
    }

    int v = x;
    #pragma unroll
    for (int o = 1; o < 32; o <<= 1) {
        int t = __shfl_up_sync(0xFFFFFFFFu, v, o);
        if ((tid & 31) >= o) v += t;
    }
    if ((tid & 31) == 31) wsum[tid >> 5] = v;
    __syncthreads();
    if (tid < 32) {
        int w = wsum[tid];
        #pragma unroll
        for (int o = 1; o < 32; o <<= 1) {
            int t = __shfl_up_sync(0xFFFFFFFFu, w, o);
            if (tid >= o) w += t;
        }
        wsum[tid] = w;
    }
    __syncthreads();
    int warppre = (tid >= 32) ? wsum[(tid >> 5) - 1] : 0;
    int incl = v + warppre;
    if (tid == 1023) s_agg = incl;
    __syncthreads();

    if (tid < 32) {
        int agg = s_agg;
        int run = 0;
        if (pb == 0) {
            if (tid == 0) atomicExch(&st[0], ((unsigned long long)agg << 2) | 2ULL);
        } else {
            if (tid == 0) atomicExch(&st[pb], ((unsigned long long)agg << 2) | 1ULL);
            __syncwarp();
            int p = pb - 1;
            while (true) {
                int idx = p - (int)tid;
                int flag;
                int val = 0;
                if (idx >= 0) {
                    unsigned long long s;
                    do { s = atomicAdd(&st[idx], 0ULL); flag = (int)(s & 3ULL); } while (flag == 0);
                    val = (int)(s >> 2);
                } else {
                    flag = 2;
                }
                unsigned m2 = __ballot_sync(0xFFFFFFFFu, flag == 2);
                int k = __ffs(m2) - 1;
                int contrib = (m2 == 0u || (int)tid <= k) ? val : 0;
                #pragma unroll
                for (int o = 16; o; o >>= 1) contrib += __shfl_down_sync(0xFFFFFFFFu, contrib, o);
                contrib = __shfl_sync(0xFFFFFFFFu, contrib, 0);
                run += contrib;
                if (m2) break;
                p -= 32;
            }
            if (tid == 0) atomicExch(&st[pb], ((unsigned long long)(agg + run) << 2) | 2ULL);
        }
        if (tid == 0) s_prefix = run;
    }
    __syncthreads();

    if (i < n) out[i] = s_prefix + incl - x;
    if (b == 0 && tid == 0) {
        g_offs_v[N_NODES] = NNZ;
        g_offs_e[N_EDGES] = NNZ;
    }
}

// ---------------- 3: CSR fill (atomic-free) + re-zero counters/states ----------------
__global__ void fill_kernel(const int* __restrict__ v_idx, const int* __restrict__ e_idx) {
    cudaTriggerProgrammaticLaunchCompletion();    // let edge_reduce launch early
    int i = blockIdx.x * blockDim.x + threadIdx.x;
    cudaGridDependencySynchronize();              // wait for offsets
    if (i < NNZ) {
        int v = v_idx[i];
        int e = e_idx[i];
        int p = g_pos[i];
        g_edge_adj[g_offs_e[e] + (p & 0xFFFF)] = v;
        g_node_adj[g_offs_v[v] + (p >> 16)] = (unsigned short)e;
    }
    if (i < N_NODES) g_cnt_v[i] = 0;
    if (i < N_EDGES) g_cnt_e[i] = 0;
    if (i < NB_V) g_state_v[i] = 0ULL;
    if (i < NB_E) g_state_e[i] = 0ULL;
}

// ---------------- 4: edge gather-reduce — LDG.128, 2 rows/warp-step ----------------
__global__ void edge_reduce_kernel() {
    cudaTriggerProgrammaticLaunchCompletion();    // let gemm launch early (W prologue)
    int gw = (blockIdx.x * blockDim.x + threadIdx.x) >> 5;
    int lane = threadIdx.x & 31;
    int half = lane >> 4;
    int c16  = lane & 15;
    cudaGridDependencySynchronize();              // wait for edge_adj
    if (gw >= N_EDGES) return;
    int beg = g_offs_e[gw], end = g_offs_e[gw + 1];
    const uint4* X4 = (const uint4*)g_Xh;          // 16 uint4 per row
    float acc[8] = {0.f, 0.f, 0.f, 0.f, 0.f, 0.f, 0.f, 0.f};
    float ssum = 0.f;
    int j = beg;
    for (; j + 8 <= end; j += 8) {                 // 4 pairs in flight
        int vv[4]; float sc[4]; uint4 q[4];
        #pragma unroll
        for (int u = 0; u < 4; u++) vv[u] = g_edge_adj[j + 2 * u + half];
        #pragma unroll
        for (int u = 0; u < 4; u++) sc[u] = g_inv_sqrt_dv[vv[u]];
        #pragma unroll
        for (int u = 0; u < 4; u++) q[u] = X4[(size_t)vv[u] * 16 + c16];
        #pragma unroll
        for (int u = 0; u < 4; u++) {
            float2 f0 = __half22float2(*reinterpret_cast<__half2*>(&q[u].x));
            float2 f1 = __half22float2(*reinterpret_cast<__half2*>(&q[u].y));
            float2 f2 = __half22float2(*reinterpret_cast<__half2*>(&q[u].z));
            float2 f3 = __half22float2(*reinterpret_cast<__half2*>(&q[u].w));
            acc[0] = fmaf(sc[u], f0.x, acc[0]);
            acc[1] = fmaf(sc[u], f0.y, acc[1]);
            acc[2] = fmaf(sc[u], f1.x, acc[2]);
            acc[3] = fmaf(sc[u], f1.y, acc[3]);
            acc[4] = fmaf(sc[u], f2.x, acc[4]);
            acc[5] = fmaf(sc[u], f2.y, acc[5]);
            acc[6] = fmaf(sc[u], f3.x, acc[6]);
            acc[7] = fmaf(sc[u], f3.y, acc[7]);
            ssum += sc[u];
        }
    }
    for (; j + 2 <= end; j += 2) {                 // pair tail
        int v = g_edge_adj[j + half];
        float sc = g_inv_sqrt_dv[v];
        uint4 q = X4[(size_t)v * 16 + c16];
        float2 f0 = __half22float2(*reinterpret_cast<__half2*>(&q.x));
        float2 f1 = __half22float2(*reinterpret_cast<__half2*>(&q.y));
        float2 f2 = __half22float2(*reinterpret_cast<__half2*>(&q.z));
        float2 f3 = __half22float2(*reinterpret_cast<__half2*>(&q.w));
        acc[0] = fmaf(sc, f0.x, acc[0]);
        acc[1] = fmaf(sc, f0.y, acc[1]);
        acc[2] = fmaf(sc, f1.x, acc[2]);
        acc[3] = fmaf(sc, f1.y, acc[3]);
        acc[4] = fmaf(sc, f2.x, acc[4]);
        acc[5] = fmaf(sc, f2.y, acc[5]);
        acc[6] = fmaf(sc, f3.x, acc[6]);
        acc[7] = fmaf(sc, f3.y, acc[7]);
        ssum += sc;
    }
    if (j < end && half == 0) {                    // single tail entry: group 0 only
        int v = g_edge_adj[j];
        float sc = g_inv_sqrt_dv[v];
        uint4 q = X4[(size_t)v * 16 + c16];
        float2 f0 = __half22float2(*reinterpret_cast<__half2*>(&q.x));
        float2 f1 = __half22float2(*reinterpret_cast<__half2*>(&q.y));
        float2 f2 = __half22float2(*reinterpret_cast<__half2*>(&q.z));
        float2 f3 = __half22float2(*reinterpret_cast<__half2*>(&q.w));
        acc[0] = fmaf(sc, f0.x, acc[0]);
        acc[1] = fmaf(sc, f0.y, acc[1]);
        acc[2] = fmaf(sc, f1.x, acc[2]);
        acc[3] = fmaf(sc, f1.y, acc[3]);
        acc[4] = fmaf(sc, f2.x, acc[4]);
        acc[5] = fmaf(sc, f2.y, acc[5]);
        acc[6] = fmaf(sc, f3.x, acc[6]);
        acc[7] = fmaf(sc, f3.y, acc[7]);
        ssum += sc;
    }
    #pragma unroll
    for (int k = 0; k < 8; k++) acc[k] += __shfl_xor_sync(0xFFFFFFFFu, acc[k], 16);
    ssum += __shfl_xor_sync(0xFFFFFFFFu, ssum, 16);
    float s = g_inv_de[gw];
    if (half == 0) {                               // lanes 0-15 write the row
        float* rp = g_Yp + (size_t)gw * D + c16 * 8;
        ((float4*)rp)[0] = make_float4(acc[0] * s, acc[1] * s, acc[2] * s, acc[3] * s);
        ((float4*)rp)[1] = make_float4(acc[4] * s, acc[5] * s, acc[6] * s, acc[7] * s);
        if (lane == 0) g_se[gw] = ssum * s;
    }
}

// ---------------- 5: small GEMM  Ye = Yp @ W + se * b — W-load overlapped via PDL ----------------
#define BM 64
#define XS_STRIDE 132
#define GEMM_SMEM_BYTES ((128 * 128 + BM * XS_STRIDE + 128) * 4)

__global__ void __launch_bounds__(256)
gemm_edges_kernel(const float* __restrict__ W, const float* __restrict__ bias) {
    extern __shared__ float sm[];
    float* Wsm = sm;
    float* Ysm = sm + 128 * 128;
    float* bsm = Ysm + BM * XS_STRIDE;

    cudaTriggerProgrammaticLaunchCompletion();    // let node_reduce launch early
    int tid = threadIdx.x;
    int row0 = blockIdx.x * BM;

    // prologue: W + bias loads are independent of edge_reduce -> run before sync
    for (int i = tid; i < 128 * 32; i += 256)
        ((float4*)Wsm)[i] = ((const float4*)W)[i];
    if (tid < 32)
        ((float4*)bsm)[tid] = ((const float4*)bias)[tid];

    cudaGridDependencySynchronize();              // now wait for Yp/se

    for (int i = tid; i < BM * 32; i += 256) {
        int m = i >> 5, kq = i & 31;
        int gr = row0 + m;
        float4 vv = (gr < N_EDGES) ? ((const float4*)(g_Yp + (size_t)gr * D))[kq]
                                   : make_float4(0.f, 0.f, 0.f, 0.f);
        *((float4*)(Ysm + m * XS_STRIDE + kq * 4)) = vv;
    }
    __syncthreads();

    int tx = tid & 31;
    int ty = tid >> 5;
    int c0 = tx * 4, r0 = ty * 8;

    float acc[8][4];
    #pragma unroll
    for (int j = 0; j < 8; j++) {
        acc[j][0] = 0.f; acc[j][1] = 0.f; acc[j][2] = 0.f; acc[j][3] = 0.f;
    }

    #pragma unroll 8
    for (int k = 0; k < 128; k++) {
        float4 b4 = *(const float4*)(Wsm + k * 128 + c0);
        #pragma unroll
        for (int j = 0; j < 8; j++) {
            float a = Ysm[(r0 + j) * XS_STRIDE + k];
            acc[j][0] = fmaf(a, b4.x, acc[j][0]);
            acc[j][1] = fmaf(a, b4.y, acc[j][1]);
            acc[j][2] = fmaf(a, b4.z, acc[j][2]);
            acc[j][3] = fmaf(a, b4.w, acc[j][3]);
        }
    }

    float4 bb = *(const float4*)(bsm + c0);
    #pragma unroll
    for (int j = 0; j < 8; j++) {
        int gr = row0 + r0 + j;
        if (gr < N_EDGES) {
            float se = g_se[gr];
            float ox = fmaf(se, bb.x, acc[j][0]);
            float oy = fmaf(se, bb.y, acc[j][1]);
            float oz = fmaf(se, bb.z, acc[j][2]);
            float ow = fmaf(se, bb.w, acc[j][3]);
            __half2 h0 = __floats2half2_rn(ox, oy);
            __half2 h1 = __floats2half2_rn(oz, ow);
            uint2 r;
            r.x = *reinterpret_cast<const unsigned*>(&h0);
            r.y = *reinterpret_cast<const unsigned*>(&h1);
            ((uint2*)g_Yeh)[(size_t)gr * 32 + tx] = r;
        }
    }
}

// ---------------- 6: node gather-reduce — LDG.128, 2 rows/warp-step + relu ----------------
__global__ void node_reduce_kernel(float* __restrict__ out) {
    int gw = (blockIdx.x * blockDim.x + threadIdx.x) >> 5;
    int lane = threadIdx.x & 31;
    int half = lane >> 4;
    int c16  = lane & 15;
    cudaGridDependencySynchronize();              // wait for Yeh
    if (gw >= N_NODES) return;
    int beg = g_offs_v[gw], end = g_offs_v[gw + 1];
    const uint4* Ye4 = (const uint4*)g_Yeh;        // 16 uint4 per row
    float acc[8] = {0.f, 0.f, 0.f, 0.f, 0.f, 0.f, 0.f, 0.f};
    int j = beg;
    for (; j + 8 <= end; j += 8) {
        int ee[4]; uint4 q[4];
        #pragma unroll
        for (int u = 0; u < 4; u++) ee[u] = g_node_adj[j + 2 * u + half];
        #pragma unroll
        for (int u = 0; u < 4; u++) q[u] = Ye4[(size_t)ee[u] * 16 + c16];
        #pragma unroll
        for (int u = 0; u < 4; u++) {
            float2 f0 = __half22float2(*reinterpret_cast<__half2*>(&q[u].x));
            float2 f1 = __half22float2(*reinterpret_cast<__half2*>(&q[u].y));
            float2 f2 = __half22float2(*reinterpret_cast<__half2*>(&q[u].z));
            float2 f3 = __half22float2(*reinterpret_cast<__half2*>(&q[u].w));
            acc[0] += f0.x; acc[1] += f0.y; acc[2] += f1.x; acc[3] += f1.y;
            acc[4] += f2.x; acc[5] += f2.y; acc[6] += f3.x; acc[7] += f3.y;
        }
    }
    for (; j + 2 <= end; j += 2) {
        int e = g_node_adj[j + half];
        uint4 q = Ye4[(size_t)e * 16 + c16];
        float2 f0 = __half22float2(*reinterpret_cast<__half2*>(&q.x));
        float2 f1 = __half22float2(*reinterpret_cast<__half2*>(&q.y));
        float2 f2 = __half22float2(*reinterpret_cast<__half2*>(&q.z));
        float2 f3 = __half22float2(*reinterpret_cast<__half2*>(&q.w));
        acc[0] += f0.x; acc[1] += f0.y; acc[2] += f1.x; acc[3] += f1.y;
        acc[4] += f2.x; acc[5] += f2.y; acc[6] += f3.x; acc[7] += f3.y;
    }
    if (j < end && half == 0) {
        int e = g_node_adj[j];
        uint4 q = Ye4[(size_t)e * 16 + c16];
        float2 f0 = __half22float2(*reinterpret_cast<__half2*>(&q.x));
        float2 f1 = __half22float2(*reinterpret_cast<__half2*>(&q.y));
        float2 f2 = __half22float2(*reinterpret_cast<__half2*>(&q.z));
        float2 f3 = __half22float2(*reinterpret_cast<__half2*>(&q.w));
        acc[0] += f0.x; acc[1] += f0.y; acc[2] += f1.x; acc[3] += f1.y;
        acc[4] += f2.x; acc[5] += f2.y; acc[6] += f3.x; acc[7] += f3.y;
    }
    #pragma unroll
    for (int k = 0; k < 8; k++) acc[k] += __shfl_xor_sync(0xFFFFFFFFu, acc[k], 16);
    if (half == 0) {
        float s = g_inv_sqrt_dv[gw];
        float* rp = out + (size_t)gw * D + c16 * 8;
        ((float4*)rp)[0] = make_float4(fmaxf(acc[0] * s, 0.f), fmaxf(acc[1] * s, 0.f),
                                       fmaxf(acc[2] * s, 0.f), fmaxf(acc[3] * s, 0.f));
        ((float4*)rp)[1] = make_float4(fmaxf(acc[4] * s, 0.f), fmaxf(acc[5] * s, 0.f),
                                       fmaxf(acc[6] * s, 0.f), fmaxf(acc[7] * s, 0.f));
    }
}

// ---------------- launch: PDL chain with early triggers ----------------
static inline void launch_pdl(void* fn, dim3 grid, dim3 block, size_t smem,
                              void** args) {
    cudaLaunchConfig_t cfg = {};
    cfg.gridDim = grid;
    cfg.blockDim = block;
    cfg.dynamicSmemBytes = smem;
    cfg.stream = 0;
    cudaLaunchAttribute attr[1];
    attr[0].id = cudaLaunchAttributeProgrammaticStreamSerialization;
    attr[0].val.programmaticStreamSerializationAllowed = 1;
    cfg.attrs = attr;
    cfg.numAttrs = 1;
    cudaLaunchKernelExC(&cfg, fn, args);
}

extern "C" void kernel_launch(void* const* d_in, const int* in_sizes, int n_in,
                              void* d_out, int out_size) {
    const float* X     = (const float*)d_in[0];
    const float* W     = (const float*)d_in[1];
    const float* bias  = (const float*)d_in[2];
    const int*   v_idx = (const int*)d_in[3];
    const int*   e_idx = (const int*)d_in[4];
    float* out = (float*)d_out;

    (void)in_sizes; (void)n_in; (void)out_size;

    cudaFuncSetAttribute(gemm_edges_kernel, cudaFuncAttributeMaxDynamicSharedMemorySize,
                         GEMM_SMEM_BYTES);

    degree_convert_kernel<<<(N_NODES * 32 + 255) / 256, 256>>>(X, v_idx, e_idx);

    {   // scan (PDL)
        void* args[] = {};
        launch_pdl((void*)scan_fused_kernel, dim3(NB_V + NB_E), dim3(1024), 0, args);
    }
    {   // fill (PDL)
        void* args[] = {(void*)&v_idx, (void*)&e_idx};
        launch_pdl((void*)fill_kernel, dim3((NNZ + 255) / 256), dim3(256), 0, args);
    }
    {   // edge reduce (PDL)
        void* args[] = {};
        launch_pdl((void*)edge_reduce_kernel, dim3((N_EDGES * 32 + 255) / 256), dim3(256), 0, args);
    }
    {   // gemm (PDL; W-load prologue overlaps edge_reduce tail)
        void* args[] = {(void*)&W, (void*)&bias};
        launch_pdl((void*)gemm_edges_kernel, dim3((N_EDGES + BM - 1) / BM), dim3(256),
                   GEMM_SMEM_BYTES, args);
    }
    {   // node reduce (PDL)
        void* args[] = {(void*)&out};
        launch_pdl((void*)node_reduce_kernel, dim3((N_NODES * 32 + 255) / 256), dim3(256), 0, args);
    }
}

// round 12
// speedup vs baseline: 1.0361x; 1.0361x over previous
#include <cuda_runtime.h>
#include <cuda_fp16.h>
#include <math.h>

#define N_NODES 100000
#define N_EDGES 20000
#define NNZ     1600000
#define D       128
#define NB_V    ((N_NODES + 1023) / 1024)   // 98
#define NB_E    ((N_EDGES + 1023) / 1024)   // 20

// ---------------- scratch (device globals: allocation-free rule) ----------------
// Invariant: g_cnt_v/g_cnt_e/g_state_v/g_state_e are ZERO at entry (statically
// zero-initialized; re-zeroed by fill_kernel after last use each execution).
__device__ int   g_cnt_v[N_NODES];
__device__ int   g_cnt_e[N_EDGES];
__device__ unsigned long long g_state_v[NB_V];    // lookback: (value<<2)|flag
__device__ unsigned long long g_state_e[NB_E];
__device__ int   g_offs_v[N_NODES + 1];
__device__ int   g_offs_e[N_EDGES + 1];
__device__ int   g_pos[NNZ];                      // (pos_v << 16) | pos_e
__device__ float g_inv_sqrt_dv[N_NODES];
__device__ float g_inv_de[N_EDGES];
__device__ int   g_edge_adj[NNZ];                 // per-edge list of vertex ids
__device__ unsigned short g_node_adj[NNZ];        // per-node list of edge ids (<2^16)
__device__ unsigned g_Xh[(size_t)N_NODES * 64];   // X in half2 bit patterns
__device__ float g_Yp[(size_t)N_EDGES * D];       // inv_de * H^T Dv^-1/2 X (fp32)
__device__ float g_se[N_EDGES];                   // inv_de * H^T Dv^-1/2 1
__device__ unsigned g_Yeh[(size_t)N_EDGES * 64];  // Ye in half2

// ---------------- 1: degree histograms + rank capture + X->half2 convert ----------------
__global__ void degree_convert_kernel(const float* __restrict__ X,
                                      const int* __restrict__ v_idx,
                                      const int* __restrict__ e_idx) {
    cudaTriggerProgrammaticLaunchCompletion();
    int i = blockIdx.x * blockDim.x + threadIdx.x;   // grid covers N_NODES*32
    if (i < N_NODES * 32) {
        float4 p = __ldcs(((const float4*)X) + i);   // evict-first: X is read once
        __half2 a = __floats2half2_rn(p.x, p.y);
        __half2 b = __floats2half2_rn(p.z, p.w);
        uint2 r;
        r.x = *reinterpret_cast<const unsigned*>(&a);
        r.y = *reinterpret_cast<const unsigned*>(&b);
        ((uint2*)g_Xh)[i] = r;
    }
    if (i < NNZ) {
        int pv = atomicAdd(&g_cnt_v[v_idx[i]], 1);
        int pe = atomicAdd(&g_cnt_e[e_idx[i]], 1);
        g_pos[i] = (pv << 16) | pe;
    }
}

// ---------------- 2: single-pass decoupled-lookback scan (both arrays) + inv factors ----------------
__global__ void scan_fused_kernel() {
    __shared__ int wsum[32];
    __shared__ int s_agg;
    __shared__ int s_prefix;
    int tid = threadIdx.x;                        // 1024
    int b = blockIdx.x;
    cudaTriggerProgrammaticLaunchCompletion();
    int chain_e = (b >= NB_V);
    int pb = chain_e ? (b - NB_V) : b;
    const int* in   = chain_e ? g_cnt_e : g_cnt_v;
    int*       out  = chain_e ? g_offs_e : g_offs_v;
    int        n    = chain_e ? N_EDGES : N_NODES;
    unsigned long long* st = chain_e ? g_state_e : g_state_v;

    int i = pb * 1024 + tid;

    cudaGridDependencySynchronize();              // wait for degree counts

    int x = (i < n) ? in[i] : 0;

    if (i < n) {
        if (chain_e) g_inv_de[i] = (x > 0) ? (1.0f / (float)x) : 0.0f;
        else         g_inv_sqrt_dv[i] = (x > 0) ? rsqrtf((float)x) : 0.0f;
    }

    int v = x;
    #pragma unroll
    for (int o = 1; o < 32; o <<= 1) {
        int t = __shfl_up_sync(0xFFFFFFFFu, v, o);
        if ((tid & 31) >= o) v += t;
    }
    if ((tid & 31) == 31) wsum[tid >> 5] = v;
    __syncthreads();
    if (tid < 32) {
        int w = wsum[tid];
        #pragma unroll
        for (int o = 1; o < 32; o <<= 1) {
            int t = __shfl_up_sync(0xFFFFFFFFu, w, o);
            if (tid >= o) w += t;
        }
        wsum[tid] = w;
    }
    __syncthreads();
    int warppre = (tid >= 32) ? wsum[(tid >> 5) - 1] : 0;
    int incl = v + warppre;
    if (tid == 1023) s_agg = incl;
    __syncthreads();

    if (tid < 32) {
        int agg = s_agg;
        int run = 0;
        if (pb == 0) {
            if (tid == 0) atomicExch(&st[0], ((unsigned long long)agg << 2) | 2ULL);
        } else {
            if (tid == 0) atomicExch(&st[pb], ((unsigned long long)agg << 2) | 1ULL);
            __syncwarp();
            int p = pb - 1;
            while (true) {
                int idx = p - (int)tid;
                int flag;
                int val = 0;
                if (idx >= 0) {
                    unsigned long long s;
                    do { s = atomicAdd(&st[idx], 0ULL); flag = (int)(s & 3ULL); } while (flag == 0);
                    val = (int)(s >> 2);
                } else {
                    flag = 2;
                }
                unsigned m2 = __ballot_sync(0xFFFFFFFFu, flag == 2);
                int k = __ffs(m2) - 1;
                int contrib = (m2 == 0u || (int)tid <= k) ? val : 0;
                #pragma unroll
                for (int o = 16; o; o >>= 1) contrib += __shfl_down_sync(0xFFFFFFFFu, contrib, o);
                contrib = __shfl_sync(0xFFFFFFFFu, contrib, 0);
                run += contrib;
                if (m2) break;
                p -= 32;
            }
            if (tid == 0) atomicExch(&st[pb], ((unsigned long long)(agg + run) << 2) | 2ULL);
        }
        if (tid == 0) s_prefix = run;
    }
    __syncthreads();

    if (i < n) out[i] = s_prefix + incl - x;
    if (b == 0 && tid == 0) {
        g_offs_v[N_NODES] = NNZ;
        g_offs_e[N_EDGES] = NNZ;
    }
}

// ---------------- 3: CSR fill (atomic-free) + re-zero counters/states ----------------
__global__ void fill_kernel(const int* __restrict__ v_idx, const int* __restrict__ e_idx) {
    cudaTriggerProgrammaticLaunchCompletion();
    int i = blockIdx.x * blockDim.x + threadIdx.x;
    cudaGridDependencySynchronize();              // wait for offsets
    if (i < NNZ) {
        int v = v_idx[i];
        int e = e_idx[i];
        int p = g_pos[i];
        g_edge_adj[g_offs_e[e] + (p & 0xFFFF)] = v;
        g_node_adj[g_offs_v[v] + (p >> 16)] = (unsigned short)e;
    }
    if (i < N_NODES) g_cnt_v[i] = 0;
    if (i < N_EDGES) g_cnt_e[i] = 0;
    if (i < NB_V) g_state_v[i] = 0ULL;
    if (i < NB_E) g_state_e[i] = 0ULL;
}

// ---------------- 4: edge gather-reduce — LDG.128, 8 rows in flight per group ----------------
// warp = one edge. lanes split into two 16-lane groups; group g handles 8
// contiguous entries per 16-entry step; each lane reads 16B chunk c16 of a row.
__global__ void edge_reduce_kernel() {
    cudaTriggerProgrammaticLaunchCompletion();
    int gw = (blockIdx.x * blockDim.x + threadIdx.x) >> 5;
    int lane = threadIdx.x & 31;
    int half = lane >> 4;
    int c16  = lane & 15;
    cudaGridDependencySynchronize();              // wait for edge_adj
    if (gw >= N_EDGES) return;
    int beg = g_offs_e[gw], end = g_offs_e[gw + 1];
    const uint4* X4 = (const uint4*)g_Xh;          // 16 uint4 per row
    float acc[8] = {0.f, 0.f, 0.f, 0.f, 0.f, 0.f, 0.f, 0.f};
    float ssum = 0.f;
    int j = beg;
    for (; j + 16 <= end; j += 16) {               // 8 rows in flight per group
        int base = j + half * 8;
        int vv[8]; float sc[8]; uint4 q[8];
        #pragma unroll
        for (int u = 0; u < 8; u++) vv[u] = g_edge_adj[base + u];
        #pragma unroll
        for (int u = 0; u < 8; u++) sc[u] = g_inv_sqrt_dv[vv[u]];
        #pragma unroll
        for (int u = 0; u < 8; u++) q[u] = X4[(size_t)vv[u] * 16 + c16];
        #pragma unroll
        for (int u = 0; u < 8; u++) {
            float2 f0 = __half22float2(*reinterpret_cast<__half2*>(&q[u].x));
            float2 f1 = __half22float2(*reinterpret_cast<__half2*>(&q[u].y));
            float2 f2 = __half22float2(*reinterpret_cast<__half2*>(&q[u].z));
            float2 f3 = __half22float2(*reinterpret_cast<__half2*>(&q[u].w));
            acc[0] = fmaf(sc[u], f0.x, acc[0]);
            acc[1] = fmaf(sc[u], f0.y, acc[1]);
            acc[2] = fmaf(sc[u], f1.x, acc[2]);
            acc[3] = fmaf(sc[u], f1.y, acc[3]);
            acc[4] = fmaf(sc[u], f2.x, acc[4]);
            acc[5] = fmaf(sc[u], f2.y, acc[5]);
            acc[6] = fmaf(sc[u], f3.x, acc[6]);
            acc[7] = fmaf(sc[u], f3.y, acc[7]);
            ssum += sc[u];
        }
    }
    for (; j + 2 <= end; j += 2) {                 // pair tail
        int v = g_edge_adj[j + half];
        float sc = g_inv_sqrt_dv[v];
        uint4 q = X4[(size_t)v * 16 + c16];
        float2 f0 = __half22float2(*reinterpret_cast<__half2*>(&q.x));
        float2 f1 = __half22float2(*reinterpret_cast<__half2*>(&q.y));
        float2 f2 = __half22float2(*reinterpret_cast<__half2*>(&q.z));
        float2 f3 = __half22float2(*reinterpret_cast<__half2*>(&q.w));
        acc[0] = fmaf(sc, f0.x, acc[0]);
        acc[1] = fmaf(sc, f0.y, acc[1]);
        acc[2] = fmaf(sc, f1.x, acc[2]);
        acc[3] = fmaf(sc, f1.y, acc[3]);
        acc[4] = fmaf(sc, f2.x, acc[4]);
        acc[5] = fmaf(sc, f2.y, acc[5]);
        acc[6] = fmaf(sc, f3.x, acc[6]);
        acc[7] = fmaf(sc, f3.y, acc[7]);
        ssum += sc;
    }
    if (j < end && half == 0) {                    // single tail entry
        int v = g_edge_adj[j];
        float sc = g_inv_sqrt_dv[v];
        uint4 q = X4[(size_t)v * 16 + c16];
        float2 f0 = __half22float2(*reinterpret_cast<__half2*>(&q.x));
        float2 f1 = __half22float2(*reinterpret_cast<__half2*>(&q.y));
        float2 f2 = __half22float2(*reinterpret_cast<__half2*>(&q.z));
        float2 f3 = __half22float2(*reinterpret_cast<__half2*>(&q.w));
        acc[0] = fmaf(sc, f0.x, acc[0]);
        acc[1] = fmaf(sc, f0.y, acc[1]);
        acc[2] = fmaf(sc, f1.x, acc[2]);
        acc[3] = fmaf(sc, f1.y, acc[3]);
        acc[4] = fmaf(sc, f2.x, acc[4]);
        acc[5] = fmaf(sc, f2.y, acc[5]);
        acc[6] = fmaf(sc, f3.x, acc[6]);
        acc[7] = fmaf(sc, f3.y, acc[7]);
        ssum += sc;
    }
    #pragma unroll
    for (int k = 0; k < 8; k++) acc[k] += __shfl_xor_sync(0xFFFFFFFFu, acc[k], 16);
    ssum += __shfl_xor_sync(0xFFFFFFFFu, ssum, 16);
    float s = g_inv_de[gw];
    if (half == 0) {                               // lanes 0-15 write the row
        float* rp = g_Yp + (size_t)gw * D + c16 * 8;
        ((float4*)rp)[0] = make_float4(acc[0] * s, acc[1] * s, acc[2] * s, acc[3] * s);
        ((float4*)rp)[1] = make_float4(acc[4] * s, acc[5] * s, acc[6] * s, acc[7] * s);
        if (lane == 0) g_se[gw] = ssum * s;
    }
}

// ---------------- 5: small GEMM  Ye = Yp @ W + se * b — W-load overlapped via PDL ----------------
#define BM 64
#define XS_STRIDE 132
#define GEMM_SMEM_BYTES ((128 * 128 + BM * XS_STRIDE + 128) * 4)

__global__ void __launch_bounds__(256)
gemm_edges_kernel(const float* __restrict__ W, const float* __restrict__ bias) {
    extern __shared__ float sm[];
    float* Wsm = sm;
    float* Ysm = sm + 128 * 128;
    float* bsm = Ysm + BM * XS_STRIDE;

    cudaTriggerProgrammaticLaunchCompletion();
    int tid = threadIdx.x;
    int row0 = blockIdx.x * BM;

    // prologue: W + bias loads are independent of edge_reduce -> run before sync
    for (int i = tid; i < 128 * 32; i += 256)
        ((float4*)Wsm)[i] = ((const float4*)W)[i];
    if (tid < 32)
        ((float4*)bsm)[tid] = ((const float4*)bias)[tid];

    cudaGridDependencySynchronize();              // now wait for Yp/se

    for (int i = tid; i < BM * 32; i += 256) {
        int m = i >> 5, kq = i & 31;
        int gr = row0 + m;
        float4 vv = (gr < N_EDGES) ? ((const float4*)(g_Yp + (size_t)gr * D))[kq]
                                   : make_float4(0.f, 0.f, 0.f, 0.f);
        *((float4*)(Ysm + m * XS_STRIDE + kq * 4)) = vv;
    }
    __syncthreads();

    int tx = tid & 31;
    int ty = tid >> 5;
    int c0 = tx * 4, r0 = ty * 8;

    float acc[8][4];
    #pragma unroll
    for (int j = 0; j < 8; j++) {
        acc[j][0] = 0.f; acc[j][1] = 0.f; acc[j][2] = 0.f; acc[j][3] = 0.f;
    }

    #pragma unroll 8
    for (int k = 0; k < 128; k++) {
        float4 b4 = *(const float4*)(Wsm + k * 128 + c0);
        #pragma unroll
        for (int j = 0; j < 8; j++) {
            float a = Ysm[(r0 + j) * XS_STRIDE + k];
            acc[j][0] = fmaf(a, b4.x, acc[j][0]);
            acc[j][1] = fmaf(a, b4.y, acc[j][1]);
            acc[j][2] = fmaf(a, b4.z, acc[j][2]);
            acc[j][3] = fmaf(a, b4.w, acc[j][3]);
        }
    }

    float4 bb = *(const float4*)(bsm + c0);
    #pragma unroll
    for (int j = 0; j < 8; j++) {
        int gr = row0 + r0 + j;
        if (gr < N_EDGES) {
            float se = g_se[gr];
            float ox = fmaf(se, bb.x, acc[j][0]);
            float oy = fmaf(se, bb.y, acc[j][1]);
            float oz = fmaf(se, bb.z, acc[j][2]);
            float ow = fmaf(se, bb.w, acc[j][3]);
            __half2 h0 = __floats2half2_rn(ox, oy);
            __half2 h1 = __floats2half2_rn(oz, ow);
            uint2 r;
            r.x = *reinterpret_cast<const unsigned*>(&h0);
            r.y = *reinterpret_cast<const unsigned*>(&h1);
            ((uint2*)g_Yeh)[(size_t)gr * 32 + tx] = r;
        }
    }
}

// ---------------- 6: node gather-reduce — LDG.128, 8 rows in flight per group + relu ----------------
__global__ void node_reduce_kernel(float* __restrict__ out) {
    int gw = (blockIdx.x * blockDim.x + threadIdx.x) >> 5;
    int lane = threadIdx.x & 31;
    int half = lane >> 4;
    int c16  = lane & 15;
    cudaGridDependencySynchronize();              // wait for Yeh
    if (gw >= N_NODES) return;
    int beg = g_offs_v[gw], end = g_offs_v[gw + 1];
    const uint4* Ye4 = (const uint4*)g_Yeh;        // 16 uint4 per row
    float acc[8] = {0.f, 0.f, 0.f, 0.f, 0.f, 0.f, 0.f, 0.f};
    int j = beg;
    for (; j + 16 <= end; j += 16) {               // 8 rows in flight per group
        int base = j + half * 8;
        int ee[8]; uint4 q[8];
        #pragma unroll
        for (int u = 0; u < 8; u++) ee[u] = g_node_adj[base + u];
        #pragma unroll
        for (int u = 0; u < 8; u++) q[u] = Ye4[(size_t)ee[u] * 16 + c16];
        #pragma unroll
        for (int u = 0; u < 8; u++) {
            float2 f0 = __half22float2(*reinterpret_cast<__half2*>(&q[u].x));
            float2 f1 = __half22float2(*reinterpret_cast<__half2*>(&q[u].y));
            float2 f2 = __half22float2(*reinterpret_cast<__half2*>(&q[u].z));
            float2 f3 = __half22float2(*reinterpret_cast<__half2*>(&q[u].w));
            acc[0] += f0.x; acc[1] += f0.y; acc[2] += f1.x; acc[3] += f1.y;
            acc[4] += f2.x; acc[5] += f2.y; acc[6] += f3.x; acc[7] += f3.y;
        }
    }
    for (; j + 2 <= end; j += 2) {
        int e = g_node_adj[j + half];
        uint4 q = Ye4[(size_t)e * 16 + c16];
        float2 f0 = __half22float2(*reinterpret_cast<__half2*>(&q.x));
        float2 f1 = __half22float2(*reinterpret_cast<__half2*>(&q.y));
        float2 f2 = __half22float2(*reinterpret_cast<__half2*>(&q.z));
        float2 f3 = __half22float2(*reinterpret_cast<__half2*>(&q.w));
        acc[0] += f0.x; acc[1] += f0.y; acc[2] += f1.x; acc[3] += f1.y;
        acc[4] += f2.x; acc[5] += f2.y; acc[6] += f3.x; acc[7] += f3.y;
    }
    if (j < end && half == 0) {
        int e = g_node_adj[j];
        uint4 q = Ye4[(size_t)e * 16 + c16];
        float2 f0 = __half22float2(*reinterpret_cast<__half2*>(&q.x));
        float2 f1 = __half22float2(*reinterpret_cast<__half2*>(&q.y));
        float2 f2 = __half22float2(*reinterpret_cast<__half2*>(&q.z));
        float2 f3 = __half22float2(*reinterpret_cast<__half2*>(&q.w));
        acc[0] += f0.x; acc[1] += f0.y; acc[2] += f1.x; acc[3] += f1.y;
        acc[4] += f2.x; acc[5] += f2.y; acc[6] += f3.x; acc[7] += f3.y;
    }
    #pragma unroll
    for (int k = 0; k < 8; k++) acc[k] += __shfl_xor_sync(0xFFFFFFFFu, acc[k], 16);
    if (half == 0) {
        float s = g_inv_sqrt_dv[gw];
        float* rp = out + (size_t)gw * D + c16 * 8;
        ((float4*)rp)[0] = make_float4(fmaxf(acc[0] * s, 0.f), fmaxf(acc[1] * s, 0.f),
                                       fmaxf(acc[2] * s, 0.f), fmaxf(acc[3] * s, 0.f));
        ((float4*)rp)[1] = make_float4(fmaxf(acc[4] * s, 0.f), fmaxf(acc[5] * s, 0.f),
                                       fmaxf(acc[6] * s, 0.f), fmaxf(acc[7] * s, 0.f));
    }
}

// ---------------- launch: PDL chain with early triggers ----------------
static inline void launch_pdl(void* fn, dim3 grid, dim3 block, size_t smem,
                              void** args) {
    cudaLaunchConfig_t cfg = {};
    cfg.gridDim = grid;
    cfg.blockDim = block;
    cfg.dynamicSmemBytes = smem;
    cfg.stream = 0;
    cudaLaunchAttribute attr[1];
    attr[0].id = cudaLaunchAttributeProgrammaticStreamSerialization;
    attr[0].val.programmaticStreamSerializationAllowed = 1;
    cfg.attrs = attr;
    cfg.numAttrs = 1;
    cudaLaunchKernelExC(&cfg, fn, args);
}

extern "C" void kernel_launch(void* const* d_in, const int* in_sizes, int n_in,
                              void* d_out, int out_size) {
    const float* X     = (const float*)d_in[0];
    const float* W     = (const float*)d_in[1];
    const float* bias  = (const float*)d_in[2];
    const int*   v_idx = (const int*)d_in[3];
    const int*   e_idx = (const int*)d_in[4];
    float* out = (float*)d_out;

    (void)in_sizes; (void)n_in; (void)out_size;

    cudaFuncSetAttribute(gemm_edges_kernel, cudaFuncAttributeMaxDynamicSharedMemorySize,
                         GEMM_SMEM_BYTES);

    degree_convert_kernel<<<(N_NODES * 32 + 255) / 256, 256>>>(X, v_idx, e_idx);

    {   // scan (PDL)
        void* args[] = {};
        launch_pdl((void*)scan_fused_kernel, dim3(NB_V + NB_E), dim3(1024), 0, args);
    }
    {   // fill (PDL)
        void* args[] = {(void*)&v_idx, (void*)&e_idx};
        launch_pdl((void*)fill_kernel, dim3((NNZ + 255) / 256), dim3(256), 0, args);
    }
    {   // edge reduce (PDL)
        void* args[] = {};
        launch_pdl((void*)edge_reduce_kernel, dim3((N_EDGES * 32 + 255) / 256), dim3(256), 0, args);
    }
    {   // gemm (PDL; W-load prologue overlaps edge_reduce tail)
        void* args[] = {(void*)&W, (void*)&bias};
        launch_pdl((void*)gemm_edges_kernel, dim3((N_EDGES + BM - 1) / BM), dim3(256),
                   GEMM_SMEM_BYTES, args);
    }
    {   // node reduce (PDL)
        void* args[] = {(void*)&out};
        launch_pdl((void*)node_reduce_kernel, dim3((N_NODES * 32 + 255) / 256), dim3(256), 0, args);
    }
}

// round 13
// speedup vs baseline: 1.0428x; 1.0064x over previous
#include <cuda_runtime.h>
#include <cuda_fp16.h>
#include <math.h>

#define N_NODES 100000
#define N_EDGES 20000
#define NNZ     1600000
#define D       128
#define NB_V    ((N_NODES + 1023) / 1024)   // 98
#define NB_E    ((N_EDGES + 1023) / 1024)   // 20

// ---------------- scratch (device globals: allocation-free rule) ----------------
// Invariant: g_cnt_v/g_cnt_e/g_state_v/g_state_e are ZERO at entry (statically
// zero-initialized; re-zeroed by fill_kernel after last use each execution).
__device__ int   g_cnt_v[N_NODES];
__device__ int   g_cnt_e[N_EDGES];
__device__ unsigned long long g_state_v[NB_V];    // lookback: (value<<2)|flag
__device__ unsigned long long g_state_e[NB_E];
__device__ int   g_offs_v[N_NODES + 1];
__device__ int   g_offs_e[N_EDGES + 1];
__device__ int   g_pos[NNZ];                      // (pos_v << 16) | pos_e
__device__ float g_inv_sqrt_dv[N_NODES];
__device__ float g_inv_de[N_EDGES];
__device__ int   g_edge_adj[NNZ];                 // per-edge list of vertex ids
__device__ unsigned short g_node_adj[NNZ];        // per-node list of edge ids (<2^16)
__device__ unsigned g_Xh[(size_t)N_NODES * 64];   // X in half2 bit patterns
__device__ unsigned g_Yph[(size_t)N_EDGES * 64];  // Yp in half2 (edge aggregates)
__device__ float g_se[N_EDGES];                   // inv_de * H^T Dv^-1/2 1
__device__ unsigned g_Yeh[(size_t)N_EDGES * 64];  // Ye in half2

// ---------------- 1: degree histograms + rank capture + X->half2 convert ----------------
__global__ void degree_convert_kernel(const float* __restrict__ X,
                                      const int* __restrict__ v_idx,
                                      const int* __restrict__ e_idx) {
    cudaTriggerProgrammaticLaunchCompletion();
    int i = blockIdx.x * blockDim.x + threadIdx.x;   // grid covers N_NODES*32
    if (i < N_NODES * 32) {
        float4 p = __ldcs(((const float4*)X) + i);   // evict-first: X is read once
        __half2 a = __floats2half2_rn(p.x, p.y);
        __half2 b = __floats2half2_rn(p.z, p.w);
        uint2 r;
        r.x = *reinterpret_cast<const unsigned*>(&a);
        r.y = *reinterpret_cast<const unsigned*>(&b);
        ((uint2*)g_Xh)[i] = r;
    }
    if (i < NNZ) {
        int pv = atomicAdd(&g_cnt_v[v_idx[i]], 1);
        int pe = atomicAdd(&g_cnt_e[e_idx[i]], 1);
        g_pos[i] = (pv << 16) | pe;
    }
}

// ---------------- 2: single-pass decoupled-lookback scan (both arrays) + inv factors ----------------
__global__ void scan_fused_kernel() {
    __shared__ int wsum[32];
    __shared__ int s_agg;
    __shared__ int s_prefix;
    int tid = threadIdx.x;                        // 1024
    int b = blockIdx.x;
    cudaTriggerProgrammaticLaunchCompletion();
    int chain_e = (b >= NB_V);
    int pb = chain_e ? (b - NB_V) : b;
    const int* in   = chain_e ? g_cnt_e : g_cnt_v;
    int*       out  = chain_e ? g_offs_e : g_offs_v;
    int        n    = chain_e ? N_EDGES : N_NODES;
    unsigned long long* st = chain_e ? g_state_e : g_state_v;

    int i = pb * 1024 + tid;

    cudaGridDependencySynchronize();              // wait for degree counts

    int x = (i < n) ? in[i] : 0;

    if (i < n) {
        if (chain_e) g_inv_de[i] = (x > 0) ? (1.0f / (float)x) : 0.0f;
        else         g_inv_sqrt_dv[i] = (x > 0) ? rsqrtf((float)x) : 0.0f;
    }

    int v = x;
    #pragma unroll
    for (int o = 1; o < 32; o <<= 1) {
        int t = __shfl_up_sync(0xFFFFFFFFu, v, o);
        if ((tid & 31) >= o) v += t;
    }
    if ((tid & 31) == 31) wsum[tid >> 5] = v;
    __syncthreads();
    if (tid < 32) {
        int w = wsum[tid];
        #pragma unroll
        for (int o = 1; o < 32; o <<= 1) {
            int t = __shfl_up_sync(0xFFFFFFFFu, w, o);
            if (tid >= o) w += t;
        }
        wsum[tid] = w;
    }
    __syncthreads();
    int warppre = (tid >= 32) ? wsum[(tid >> 5) - 1] : 0;
    int incl = v + warppre;
    if (tid == 1023) s_agg = incl;
    __syncthreads();

    if (tid < 32) {
        int agg = s_agg;
        int run = 0;
        if (pb == 0) {
            if (tid == 0) atomicExch(&st[0], ((unsigned long long)agg << 2) | 2ULL);
        } else {
            if (tid == 0) atomicExch(&st[pb], ((unsigned long long)agg << 2) | 1ULL);
            __syncwarp();
            int p = pb - 1;
            while (true) {
                int idx = p - (int)tid;
                int flag;
                int val = 0;
                if (idx >= 0) {
                    unsigned long long s;
                    do { s = atomicAdd(&st[idx], 0ULL); flag = (int)(s & 3ULL); } while (flag == 0);
                    val = (int)(s >> 2);
                } else {
                    flag = 2;
                }
                unsigned m2 = __ballot_sync(0xFFFFFFFFu, flag == 2);
                int k = __ffs(m2) - 1;
                int contrib = (m2 == 0u || (int)tid <= k) ? val : 0;
                #pragma unroll
                for (int o = 16; o; o >>= 1) contrib += __shfl_down_sync(0xFFFFFFFFu, contrib, o);
                contrib = __shfl_sync(0xFFFFFFFFu, contrib, 0);
                run += contrib;
                if (m2) break;
                p -= 32;
            }
            if (tid == 0) atomicExch(&st[pb], ((unsigned long long)(agg + run) << 2) | 2ULL);
        }
        if (tid == 0) s_prefix = run;
    }
    __syncthreads();

    if (i < n) out[i] = s_prefix + incl - x;
    if (b == 0 && tid == 0) {
        g_offs_v[N_NODES] = NNZ;
        g_offs_e[N_EDGES] = NNZ;
    }
}

// ---------------- 3: CSR fill (atomic-free) + re-zero counters/states ----------------
__global__ void fill_kernel(const int* __restrict__ v_idx, const int* __restrict__ e_idx) {
    cudaTriggerProgrammaticLaunchCompletion();
    int i = blockIdx.x * blockDim.x + threadIdx.x;
    cudaGridDependencySynchronize();              // wait for offsets
    if (i < NNZ) {
        int v = v_idx[i];
        int e = e_idx[i];
        int p = g_pos[i];
        g_edge_adj[g_offs_e[e] + (p & 0xFFFF)] = v;
        g_node_adj[g_offs_v[v] + (p >> 16)] = (unsigned short)e;
    }
    if (i < N_NODES) g_cnt_v[i] = 0;
    if (i < N_EDGES) g_cnt_e[i] = 0;
    if (i < NB_V) g_state_v[i] = 0ULL;
    if (i < NB_E) g_state_e[i] = 0ULL;
}

// ---------------- 4: edge gather-reduce — LDG.128, 8 rows in flight per group, fp16 out ----------------
__global__ void edge_reduce_kernel() {
    cudaTriggerProgrammaticLaunchCompletion();
    int gw = (blockIdx.x * blockDim.x + threadIdx.x) >> 5;
    int lane = threadIdx.x & 31;
    int half = lane >> 4;
    int c16  = lane & 15;
    cudaGridDependencySynchronize();              // wait for edge_adj
    if (gw >= N_EDGES) return;
    int beg = g_offs_e[gw], end = g_offs_e[gw + 1];
    const uint4* X4 = (const uint4*)g_Xh;          // 16 uint4 per row
    float acc[8] = {0.f, 0.f, 0.f, 0.f, 0.f, 0.f, 0.f, 0.f};
    float ssum = 0.f;
    int j = beg;
    for (; j + 16 <= end; j += 16) {               // 8 rows in flight per group
        int base = j + half * 8;
        int vv[8]; float sc[8]; uint4 q[8];
        #pragma unroll
        for (int u = 0; u < 8; u++) vv[u] = g_edge_adj[base + u];
        #pragma unroll
        for (int u = 0; u < 8; u++) sc[u] = g_inv_sqrt_dv[vv[u]];
        #pragma unroll
        for (int u = 0; u < 8; u++) q[u] = X4[(size_t)vv[u] * 16 + c16];
        #pragma unroll
        for (int u = 0; u < 8; u++) {
            float2 f0 = __half22float2(*reinterpret_cast<__half2*>(&q[u].x));
            float2 f1 = __half22float2(*reinterpret_cast<__half2*>(&q[u].y));
            float2 f2 = __half22float2(*reinterpret_cast<__half2*>(&q[u].z));
            float2 f3 = __half22float2(*reinterpret_cast<__half2*>(&q[u].w));
            acc[0] = fmaf(sc[u], f0.x, acc[0]);
            acc[1] = fmaf(sc[u], f0.y, acc[1]);
            acc[2] = fmaf(sc[u], f1.x, acc[2]);
            acc[3] = fmaf(sc[u], f1.y, acc[3]);
            acc[4] = fmaf(sc[u], f2.x, acc[4]);
            acc[5] = fmaf(sc[u], f2.y, acc[5]);
            acc[6] = fmaf(sc[u], f3.x, acc[6]);
            acc[7] = fmaf(sc[u], f3.y, acc[7]);
            ssum += sc[u];
        }
    }
    for (; j + 8 <= end; j += 8) {                 // mid tail: 4 rows per group
        int base = j + half * 4;
        int vv[4]; float sc[4]; uint4 q[4];
        #pragma unroll
        for (int u = 0; u < 4; u++) vv[u] = g_edge_adj[base + u];
        #pragma unroll
        for (int u = 0; u < 4; u++) sc[u] = g_inv_sqrt_dv[vv[u]];
        #pragma unroll
        for (int u = 0; u < 4; u++) q[u] = X4[(size_t)vv[u] * 16 + c16];
        #pragma unroll
        for (int u = 0; u < 4; u++) {
            float2 f0 = __half22float2(*reinterpret_cast<__half2*>(&q[u].x));
            float2 f1 = __half22float2(*reinterpret_cast<__half2*>(&q[u].y));
            float2 f2 = __half22float2(*reinterpret_cast<__half2*>(&q[u].z));
            float2 f3 = __half22float2(*reinterpret_cast<__half2*>(&q[u].w));
            acc[0] = fmaf(sc[u], f0.x, acc[0]);
            acc[1] = fmaf(sc[u], f0.y, acc[1]);
            acc[2] = fmaf(sc[u], f1.x, acc[2]);
            acc[3] = fmaf(sc[u], f1.y, acc[3]);
            acc[4] = fmaf(sc[u], f2.x, acc[4]);
            acc[5] = fmaf(sc[u], f2.y, acc[5]);
            acc[6] = fmaf(sc[u], f3.x, acc[6]);
            acc[7] = fmaf(sc[u], f3.y, acc[7]);
            ssum += sc[u];
        }
    }
    for (; j + 2 <= end; j += 2) {                 // pair tail
        int v = g_edge_adj[j + half];
        float sc = g_inv_sqrt_dv[v];
        uint4 q = X4[(size_t)v * 16 + c16];
        float2 f0 = __half22float2(*reinterpret_cast<__half2*>(&q.x));
        float2 f1 = __half22float2(*reinterpret_cast<__half2*>(&q.y));
        float2 f2 = __half22float2(*reinterpret_cast<__half2*>(&q.z));
        float2 f3 = __half22float2(*reinterpret_cast<__half2*>(&q.w));
        acc[0] = fmaf(sc, f0.x, acc[0]);
        acc[1] = fmaf(sc, f0.y, acc[1]);
        acc[2] = fmaf(sc, f1.x, acc[2]);
        acc[3] = fmaf(sc, f1.y, acc[3]);
        acc[4] = fmaf(sc, f2.x, acc[4]);
        acc[5] = fmaf(sc, f2.y, acc[5]);
        acc[6] = fmaf(sc, f3.x, acc[6]);
        acc[7] = fmaf(sc, f3.y, acc[7]);
        ssum += sc;
    }
    if (j < end && half == 0) {                    // single tail entry
        int v = g_edge_adj[j];
        float sc = g_inv_sqrt_dv[v];
        uint4 q = X4[(size_t)v * 16 + c16];
        float2 f0 = __half22float2(*reinterpret_cast<__half2*>(&q.x));
        float2 f1 = __half22float2(*reinterpret_cast<__half2*>(&q.y));
        float2 f2 = __half22float2(*reinterpret_cast<__half2*>(&q.z));
        float2 f3 = __half22float2(*reinterpret_cast<__half2*>(&q.w));
        acc[0] = fmaf(sc, f0.x, acc[0]);
        acc[1] = fmaf(sc, f0.y, acc[1]);
        acc[2] = fmaf(sc, f1.x, acc[2]);
        acc[3] = fmaf(sc, f1.y, acc[3]);
        acc[4] = fmaf(sc, f2.x, acc[4]);
        acc[5] = fmaf(sc, f2.y, acc[5]);
        acc[6] = fmaf(sc, f3.x, acc[6]);
        acc[7] = fmaf(sc, f3.y, acc[7]);
        ssum += sc;
    }
    #pragma unroll
    for (int k = 0; k < 8; k++) acc[k] += __shfl_xor_sync(0xFFFFFFFFu, acc[k], 16);
    ssum += __shfl_xor_sync(0xFFFFFFFFu, ssum, 16);
    float s = g_inv_de[gw];
    if (half == 0) {                               // lanes 0-15 write the fp16 row
        __half2 h0 = __floats2half2_rn(acc[0] * s, acc[1] * s);
        __half2 h1 = __floats2half2_rn(acc[2] * s, acc[3] * s);
        __half2 h2 = __floats2half2_rn(acc[4] * s, acc[5] * s);
        __half2 h3 = __floats2half2_rn(acc[6] * s, acc[7] * s);
        uint4 r;
        r.x = *reinterpret_cast<const unsigned*>(&h0);
        r.y = *reinterpret_cast<const unsigned*>(&h1);
        r.z = *reinterpret_cast<const unsigned*>(&h2);
        r.w = *reinterpret_cast<const unsigned*>(&h3);
        ((uint4*)g_Yph)[(size_t)gw * 16 + c16] = r;
        if (lane == 0) g_se[gw] = ssum * s;
    }
}

// ---------------- 5: small GEMM  Ye = Yph @ W + se * b — fp16 in, fp32 math, fp16 out ----------------
#define BM 64
#define XS_STRIDE 132
#define GEMM_SMEM_BYTES ((128 * 128 + BM * XS_STRIDE + 128) * 4)

__global__ void __launch_bounds__(256)
gemm_edges_kernel(const float* __restrict__ W, const float* __restrict__ bias) {
    extern __shared__ float sm[];
    float* Wsm = sm;
    float* Ysm = sm + 128 * 128;
    float* bsm = Ysm + BM * XS_STRIDE;

    cudaTriggerProgrammaticLaunchCompletion();
    int tid = threadIdx.x;
    int row0 = blockIdx.x * BM;

    // prologue: W + bias loads are independent of edge_reduce -> run before sync
    for (int i = tid; i < 128 * 32; i += 256)
        ((float4*)Wsm)[i] = ((const float4*)W)[i];
    if (tid < 32)
        ((float4*)bsm)[tid] = ((const float4*)bias)[tid];

    cudaGridDependencySynchronize();              // now wait for Yph/se

    // stage Yph (fp16) -> Ysm (fp32). 16 uint4 per row; 8 k-values per uint4.
    for (int i = tid; i < BM * 16; i += 256) {
        int m = i >> 4, kq = i & 15;
        int gr = row0 + m;
        uint4 q = (gr < N_EDGES) ? ((const uint4*)g_Yph)[(size_t)gr * 16 + kq]
                                 : make_uint4(0u, 0u, 0u, 0u);
        float2 f0 = __half22float2(*reinterpret_cast<__half2*>(&q.x));
        float2 f1 = __half22float2(*reinterpret_cast<__half2*>(&q.y));
        float2 f2 = __half22float2(*reinterpret_cast<__half2*>(&q.z));
        float2 f3 = __half22float2(*reinterpret_cast<__half2*>(&q.w));
        float* rp = Ysm + m * XS_STRIDE + kq * 8;
        ((float4*)rp)[0] = make_float4(f0.x, f0.y, f1.x, f1.y);
        ((float4*)rp)[1] = make_float4(f2.x, f2.y, f3.x, f3.y);
    }
    __syncthreads();

    int tx = tid & 31;
    int ty = tid >> 5;
    int c0 = tx * 4, r0 = ty * 8;

    float acc[8][4];
    #pragma unroll
    for (int j = 0; j < 8; j++) {
        acc[j][0] = 0.f; acc[j][1] = 0.f; acc[j][2] = 0.f; acc[j][3] = 0.f;
    }

    #pragma unroll 8
    for (int k = 0; k < 128; k++) {
        float4 b4 = *(const float4*)(Wsm + k * 128 + c0);
        #pragma unroll
        for (int j = 0; j < 8; j++) {
            float a = Ysm[(r0 + j) * XS_STRIDE + k];
            acc[j][0] = fmaf(a, b4.x, acc[j][0]);
            acc[j][1] = fmaf(a, b4.y, acc[j][1]);
            acc[j][2] = fmaf(a, b4.z, acc[j][2]);
            acc[j][3] = fmaf(a, b4.w, acc[j][3]);
        }
    }

    float4 bb = *(const float4*)(bsm + c0);
    #pragma unroll
    for (int j = 0; j < 8; j++) {
        int gr = row0 + r0 + j;
        if (gr < N_EDGES) {
            float se = g_se[gr];
            float ox = fmaf(se, bb.x, acc[j][0]);
            float oy = fmaf(se, bb.y, acc[j][1]);
            float oz = fmaf(se, bb.z, acc[j][2]);
            float ow = fmaf(se, bb.w, acc[j][3]);
            __half2 h0 = __floats2half2_rn(ox, oy);
            __half2 h1 = __floats2half2_rn(oz, ow);
            uint2 r;
            r.x = *reinterpret_cast<const unsigned*>(&h0);
            r.y = *reinterpret_cast<const unsigned*>(&h1);
            ((uint2*)g_Yeh)[(size_t)gr * 32 + tx] = r;
        }
    }
}

// ---------------- 6: node gather-reduce — 8-in-flight + 4-in-flight mid-tail + relu ----------------
__global__ void node_reduce_kernel(float* __restrict__ out) {
    int gw = (blockIdx.x * blockDim.x + threadIdx.x) >> 5;
    int lane = threadIdx.x & 31;
    int half = lane >> 4;
    int c16  = lane & 15;
    cudaGridDependencySynchronize();              // wait for Yeh
    if (gw >= N_NODES) return;
    int beg = g_offs_v[gw], end = g_offs_v[gw + 1];
    const uint4* Ye4 = (const uint4*)g_Yeh;        // 16 uint4 per row
    float acc[8] = {0.f, 0.f, 0.f, 0.f, 0.f, 0.f, 0.f, 0.f};
    int j = beg;
    for (; j + 16 <= end; j += 16) {               // 8 rows in flight per group
        int base = j + half * 8;
        int ee[8]; uint4 q[8];
        #pragma unroll
        for (int u = 0; u < 8; u++) ee[u] = g_node_adj[base + u];
        #pragma unroll
        for (int u = 0; u < 8; u++) q[u] = Ye4[(size_t)ee[u] * 16 + c16];
        #pragma unroll
        for (int u = 0; u < 8; u++) {
            float2 f0 = __half22float2(*reinterpret_cast<__half2*>(&q[u].x));
            float2 f1 = __half22float2(*reinterpret_cast<__half2*>(&q[u].y));
            float2 f2 = __half22float2(*reinterpret_cast<__half2*>(&q[u].z));
            float2 f3 = __half22float2(*reinterpret_cast<__half2*>(&q[u].w));
            acc[0] += f0.x; acc[1] += f0.y; acc[2] += f1.x; acc[3] += f1.y;
            acc[4] += f2.x; acc[5] += f2.y; acc[6] += f3.x; acc[7] += f3.y;
        }
    }
    for (; j + 8 <= end; j += 8) {                 // mid tail: 4 rows per group
        int base = j + half * 4;
        int ee[4]; uint4 q[4];
        #pragma unroll
        for (int u = 0; u < 4; u++) ee[u] = g_node_adj[base + u];
        #pragma unroll
        for (int u = 0; u < 4; u++) q[u] = Ye4[(size_t)ee[u] * 16 + c16];
        #pragma unroll
        for (int u = 0; u < 4; u++) {
            float2 f0 = __half22float2(*reinterpret_cast<__half2*>(&q[u].x));
            float2 f1 = __half22float2(*reinterpret_cast<__half2*>(&q[u].y));
            float2 f2 = __half22float2(*reinterpret_cast<__half2*>(&q[u].z));
            float2 f3 = __half22float2(*reinterpret_cast<__half2*>(&q[u].w));
            acc[0] += f0.x; acc[1] += f0.y; acc[2] += f1.x; acc[3] += f1.y;
            acc[4] += f2.x; acc[5] += f2.y; acc[6] += f3.x; acc[7] += f3.y;
        }
    }
    for (; j + 2 <= end; j += 2) {
        int e = g_node_adj[j + half];
        uint4 q = Ye4[(size_t)e * 16 + c16];
        float2 f0 = __half22float2(*reinterpret_cast<__half2*>(&q.x));
        float2 f1 = __half22float2(*reinterpret_cast<__half2*>(&q.y));
        float2 f2 = __half22float2(*reinterpret_cast<__half2*>(&q.z));
        float2 f3 = __half22float2(*reinterpret_cast<__half2*>(&q.w));
        acc[0] += f0.x; acc[1] += f0.y; acc[2] += f1.x; acc[3] += f1.y;
        acc[4] += f2.x; acc[5] += f2.y; acc[6] += f3.x; acc[7] += f3.y;
    }
    if (j < end && half == 0) {
        int e = g_node_adj[j];
        uint4 q = Ye4[(size_t)e * 16 + c16];
        float2 f0 = __half22float2(*reinterpret_cast<__half2*>(&q.x));
        float2 f1 = __half22float2(*reinterpret_cast<__half2*>(&q.y));
        float2 f2 = __half22float2(*reinterpret_cast<__half2*>(&q.z));
        float2 f3 = __half22float2(*reinterpret_cast<__half2*>(&q.w));
        acc[0] += f0.x; acc[1] += f0.y; acc[2] += f1.x; acc[3] += f1.y;
        acc[4] += f2.x; acc[5] += f2.y; acc[6] += f3.x; acc[7] += f3.y;
    }
    #pragma unroll
    for (int k = 0; k < 8; k++) acc[k] += __shfl_xor_sync(0xFFFFFFFFu, acc[k], 16);
    if (half == 0) {
        float s = g_inv_sqrt_dv[gw];
        float* rp = out + (size_t)gw * D + c16 * 8;
        ((float4*)rp)[0] = make_float4(fmaxf(acc[0] * s, 0.f), fmaxf(acc[1] * s, 0.f),
                                       fmaxf(acc[2] * s, 0.f), fmaxf(acc[3] * s, 0.f));
        ((float4*)rp)[1] = make_float4(fmaxf(acc[4] * s, 0.f), fmaxf(acc[5] * s, 0.f),
                                       fmaxf(acc[6] * s, 0.f), fmaxf(acc[7] * s, 0.f));
    }
}

// ---------------- launch: PDL chain with early triggers ----------------
static inline void launch_pdl(void* fn, dim3 grid, dim3 block, size_t smem,
                              void** args) {
    cudaLaunchConfig_t cfg = {};
    cfg.gridDim = grid;
    cfg.blockDim = block;
    cfg.dynamicSmemBytes = smem;
    cfg.stream = 0;
    cudaLaunchAttribute attr[1];
    attr[0].id = cudaLaunchAttributeProgrammaticStreamSerialization;
    attr[0].val.programmaticStreamSerializationAllowed = 1;
    cfg.attrs = attr;
    cfg.numAttrs = 1;
    cudaLaunchKernelExC(&cfg, fn, args);
}

extern "C" void kernel_launch(void* const* d_in, const int* in_sizes, int n_in,
                              void* d_out, int out_size) {
    const float* X     = (const float*)d_in[0];
    const float* W     = (const float*)d_in[1];
    const float* bias  = (const float*)d_in[2];
    const int*   v_idx = (const int*)d_in[3];
    const int*   e_idx = (const int*)d_in[4];
    float* out = (float*)d_out;

    (void)in_sizes; (void)n_in; (void)out_size;

    cudaFuncSetAttribute(gemm_edges_kernel, cudaFuncAttributeMaxDynamicSharedMemorySize,
                         GEMM_SMEM_BYTES);

    degree_convert_kernel<<<(N_NODES * 32 + 255) / 256, 256>>>(X, v_idx, e_idx);

    {   // scan (PDL)
        void* args[] = {};
        launch_pdl((void*)scan_fused_kernel, dim3(NB_V + NB_E), dim3(1024), 0, args);
    }
    {   // fill (PDL)
        void* args[] = {(void*)&v_idx, (void*)&e_idx};
        launch_pdl((void*)fill_kernel, dim3((NNZ + 255) / 256), dim3(256), 0, args);
    }
    {   // edge reduce (PDL)
        void* args[] = {};
        launch_pdl((void*)edge_reduce_kernel, dim3((N_EDGES * 32 + 255) / 256), dim3(256), 0, args);
    }
    {   // gemm (PDL; W-load prologue overlaps edge_reduce tail)
        void* args[] = {(void*)&W, (void*)&bias};
        launch_pdl((void*)gemm_edges_kernel, dim3((N_EDGES + BM - 1) / BM), dim3(256),
                   GEMM_SMEM_BYTES, args);
    }
    {   // node reduce (PDL)
        void* args[] = {(void*)&out};
        launch_pdl((void*)node_reduce_kernel, dim3((N_NODES * 32 + 255) / 256), dim3(256), 0, args);
    }
}

// round 14
// speedup vs baseline: 1.0596x; 1.0161x over previous
#include <cuda_runtime.h>
#include <cuda_fp16.h>
#include <math.h>

#define N_NODES 100000
#define N_EDGES 20000
#define NNZ     1600000
#define D       128
#define NB_V    ((N_NODES + 1023) / 1024)   // 98
#define NB_E    ((N_EDGES + 1023) / 1024)   // 20

// ---------------- scratch (device globals: allocation-free rule) ----------------
// Invariant: g_cnt_v/g_cnt_e/g_state_v/g_state_e are ZERO at entry (statically
// zero-initialized; re-zeroed by fill_convert_kernel after last use each execution).
__device__ int   g_cnt_v[N_NODES];
__device__ int   g_cnt_e[N_EDGES];
__device__ unsigned long long g_state_v[NB_V];    // lookback: (value<<2)|flag
__device__ unsigned long long g_state_e[NB_E];
__device__ int   g_offs_v[N_NODES + 1];
__device__ int   g_offs_e[N_EDGES + 1];
__device__ int   g_pos[NNZ];                      // (pos_v << 16) | pos_e
__device__ float g_inv_sqrt_dv[N_NODES];
__device__ float g_inv_de[N_EDGES];
__device__ int   g_edge_adj[NNZ];                 // per-edge list of vertex ids
__device__ unsigned short g_node_adj[NNZ];        // per-node list of edge ids (<2^16)
__device__ unsigned g_Xh[(size_t)N_NODES * 64];   // X in half2 bit patterns
__device__ unsigned g_Yph[(size_t)N_EDGES * 64];  // Yp in half2 (edge aggregates)
__device__ float g_se[N_EDGES];                   // inv_de * H^T Dv^-1/2 1
__device__ unsigned g_Yeh[(size_t)N_EDGES * 64];  // Ye in half2

// ---------------- 1: degree histograms + packed rank capture (2 entries/thread) ----------------
__global__ void degree_kernel(const int* __restrict__ v_idx,
                              const int* __restrict__ e_idx) {
    cudaTriggerProgrammaticLaunchCompletion();
    int t = blockIdx.x * blockDim.x + threadIdx.x;   // covers NNZ/2
    int i = t * 2;
    if (i + 1 < NNZ) {
        int2 vv = ((const int2*)v_idx)[t];
        int2 ee = ((const int2*)e_idx)[t];
        int pv0 = atomicAdd(&g_cnt_v[vv.x], 1);
        int pe0 = atomicAdd(&g_cnt_e[ee.x], 1);
        int pv1 = atomicAdd(&g_cnt_v[vv.y], 1);
        int pe1 = atomicAdd(&g_cnt_e[ee.y], 1);
        ((int2*)g_pos)[t] = make_int2((pv0 << 16) | pe0, (pv1 << 16) | pe1);
    } else if (i < NNZ) {
        int pv = atomicAdd(&g_cnt_v[v_idx[i]], 1);
        int pe = atomicAdd(&g_cnt_e[e_idx[i]], 1);
        g_pos[i] = (pv << 16) | pe;
    }
}

// ---------------- 2: single-pass decoupled-lookback scan (both arrays) + inv factors ----------------
__global__ void scan_fused_kernel() {
    __shared__ int wsum[32];
    __shared__ int s_agg;
    __shared__ int s_prefix;
    int tid = threadIdx.x;                        // 1024
    int b = blockIdx.x;
    cudaTriggerProgrammaticLaunchCompletion();
    int chain_e = (b >= NB_V);
    int pb = chain_e ? (b - NB_V) : b;
    const int* in   = chain_e ? g_cnt_e : g_cnt_v;
    int*       out  = chain_e ? g_offs_e : g_offs_v;
    int        n    = chain_e ? N_EDGES : N_NODES;
    unsigned long long* st = chain_e ? g_state_e : g_state_v;

    int i = pb * 1024 + tid;

    cudaGridDependencySynchronize();              // wait for degree counts

    int x = (i < n) ? in[i] : 0;

    if (i < n) {
        if (chain_e) g_inv_de[i] = (x > 0) ? (1.0f / (float)x) : 0.0f;
        else         g_inv_sqrt_dv[i] = (x > 0) ? rsqrtf((float)x) : 0.0f;
    }

    int v = x;
    #pragma unroll
    for (int o = 1; o < 32; o <<= 1) {
        int t = __shfl_up_sync(0xFFFFFFFFu, v, o);
        if ((tid & 31) >= o) v += t;
    }
    if ((tid & 31) == 31) wsum[tid >> 5] = v;
    __syncthreads();
    if (tid < 32) {
        int w = wsum[tid];
        #pragma unroll
        for (int o = 1; o < 32; o <<= 1) {
            int t = __shfl_up_sync(0xFFFFFFFFu, w, o);
            if (tid >= o) w += t;
        }
        wsum[tid] = w;
    }
    __syncthreads();
    int warppre = (tid >= 32) ? wsum[(tid >> 5) - 1] : 0;
    int incl = v + warppre;
    if (tid == 1023) s_agg = incl;
    __syncthreads();

    if (tid < 32) {
        int agg = s_agg;
        int run = 0;
        if (pb == 0) {
            if (tid == 0) atomicExch(&st[0], ((unsigned long long)agg << 2) | 2ULL);
        } else {
            if (tid == 0) atomicExch(&st[pb], ((unsigned long long)agg << 2) | 1ULL);
            __syncwarp();
            int p = pb - 1;
            while (true) {
                int idx = p - (int)tid;
                int flag;
                int val = 0;
                if (idx >= 0) {
                    unsigned long long s;
                    do { s = atomicAdd(&st[idx], 0ULL); flag = (int)(s & 3ULL); } while (flag == 0);
                    val = (int)(s >> 2);
                } else {
                    flag = 2;
                }
                unsigned m2 = __ballot_sync(0xFFFFFFFFu, flag == 2);
                int k = __ffs(m2) - 1;
                int contrib = (m2 == 0u || (int)tid <= k) ? val : 0;
                #pragma unroll
                for (int o = 16; o; o >>= 1) contrib += __shfl_down_sync(0xFFFFFFFFu, contrib, o);
                contrib = __shfl_sync(0xFFFFFFFFu, contrib, 0);
                run += contrib;
                if (m2) break;
                p -= 32;
            }
            if (tid == 0) atomicExch(&st[pb], ((unsigned long long)(agg + run) << 2) | 2ULL);
        }
        if (tid == 0) s_prefix = run;
    }
    __syncthreads();

    if (i < n) out[i] = s_prefix + incl - x;
    if (b == 0 && tid == 0) {
        g_offs_v[N_NODES] = NNZ;
        g_offs_e[N_EDGES] = NNZ;
    }
}

// ---------------- 3: CSR fill + X->half2 convert (DRAM/L2 roof overlap) + re-zero ----------------
__global__ void fill_convert_kernel(const float* __restrict__ X,
                                    const int* __restrict__ v_idx,
                                    const int* __restrict__ e_idx) {
    cudaTriggerProgrammaticLaunchCompletion();
    int i = blockIdx.x * blockDim.x + threadIdx.x;   // grid covers N_NODES*32
    // convert is independent of offsets -> issue before the sync
    if (i < N_NODES * 32) {
        float4 p = __ldcs(((const float4*)X) + i);   // evict-first: X read once
        __half2 a = __floats2half2_rn(p.x, p.y);
        __half2 b = __floats2half2_rn(p.z, p.w);
        uint2 r;
        r.x = *reinterpret_cast<const unsigned*>(&a);
        r.y = *reinterpret_cast<const unsigned*>(&b);
        ((uint2*)g_Xh)[i] = r;
    }
    cudaGridDependencySynchronize();              // wait for offsets
    if (i < NNZ) {
        int v = v_idx[i];
        int e = e_idx[i];
        int p = g_pos[i];
        g_edge_adj[g_offs_e[e] + (p & 0xFFFF)] = v;
        g_node_adj[g_offs_v[v] + (p >> 16)] = (unsigned short)e;
    }
    if (i < N_NODES) g_cnt_v[i] = 0;
    if (i < N_EDGES) g_cnt_e[i] = 0;
    if (i < NB_V) g_state_v[i] = 0ULL;
    if (i < NB_E) g_state_e[i] = 0ULL;
}

// ---------------- 4: edge gather-reduce — LDG.128, 8 rows in flight per group, fp16 out ----------------
__global__ void edge_reduce_kernel() {
    cudaTriggerProgrammaticLaunchCompletion();
    int gw = (blockIdx.x * blockDim.x + threadIdx.x) >> 5;
    int lane = threadIdx.x & 31;
    int half = lane >> 4;
    int c16  = lane & 15;
    cudaGridDependencySynchronize();              // wait for edge_adj + Xh
    if (gw >= N_EDGES) return;
    int beg = g_offs_e[gw], end = g_offs_e[gw + 1];
    const uint4* X4 = (const uint4*)g_Xh;          // 16 uint4 per row
    float acc[8] = {0.f, 0.f, 0.f, 0.f, 0.f, 0.f, 0.f, 0.f};
    float ssum = 0.f;
    int j = beg;
    for (; j + 16 <= end; j += 16) {               // 8 rows in flight per group
        int base = j + half * 8;
        int vv[8]; float sc[8]; uint4 q[8];
        #pragma unroll
        for (int u = 0; u < 8; u++) vv[u] = g_edge_adj[base + u];
        #pragma unroll
        for (int u = 0; u < 8; u++) sc[u] = g_inv_sqrt_dv[vv[u]];
        #pragma unroll
        for (int u = 0; u < 8; u++) q[u] = X4[(size_t)vv[u] * 16 + c16];
        #pragma unroll
        for (int u = 0; u < 8; u++) {
            float2 f0 = __half22float2(*reinterpret_cast<__half2*>(&q[u].x));
            float2 f1 = __half22float2(*reinterpret_cast<__half2*>(&q[u].y));
            float2 f2 = __half22float2(*reinterpret_cast<__half2*>(&q[u].z));
            float2 f3 = __half22float2(*reinterpret_cast<__half2*>(&q[u].w));
            acc[0] = fmaf(sc[u], f0.x, acc[0]);
            acc[1] = fmaf(sc[u], f0.y, acc[1]);
            acc[2] = fmaf(sc[u], f1.x, acc[2]);
            acc[3] = fmaf(sc[u], f1.y, acc[3]);
            acc[4] = fmaf(sc[u], f2.x, acc[4]);
            acc[5] = fmaf(sc[u], f2.y, acc[5]);
            acc[6] = fmaf(sc[u], f3.x, acc[6]);
            acc[7] = fmaf(sc[u], f3.y, acc[7]);
            ssum += sc[u];
        }
    }
    for (; j + 8 <= end; j += 8) {                 // mid tail: 4 rows per group
        int base = j + half * 4;
        int vv[4]; float sc[4]; uint4 q[4];
        #pragma unroll
        for (int u = 0; u < 4; u++) vv[u] = g_edge_adj[base + u];
        #pragma unroll
        for (int u = 0; u < 4; u++) sc[u] = g_inv_sqrt_dv[vv[u]];
        #pragma unroll
        for (int u = 0; u < 4; u++) q[u] = X4[(size_t)vv[u] * 16 + c16];
        #pragma unroll
        for (int u = 0; u < 4; u++) {
            float2 f0 = __half22float2(*reinterpret_cast<__half2*>(&q[u].x));
            float2 f1 = __half22float2(*reinterpret_cast<__half2*>(&q[u].y));
            float2 f2 = __half22float2(*reinterpret_cast<__half2*>(&q[u].z));
            float2 f3 = __half22float2(*reinterpret_cast<__half2*>(&q[u].w));
            acc[0] = fmaf(sc[u], f0.x, acc[0]);
            acc[1] = fmaf(sc[u], f0.y, acc[1]);
            acc[2] = fmaf(sc[u], f1.x, acc[2]);
            acc[3] = fmaf(sc[u], f1.y, acc[3]);
            acc[4] = fmaf(sc[u], f2.x, acc[4]);
            acc[5] = fmaf(sc[u], f2.y, acc[5]);
            acc[6] = fmaf(sc[u], f3.x, acc[6]);
            acc[7] = fmaf(sc[u], f3.y, acc[7]);
            ssum += sc[u];
        }
    }
    for (; j + 2 <= end; j += 2) {                 // pair tail
        int v = g_edge_adj[j + half];
        float sc = g_inv_sqrt_dv[v];
        uint4 q = X4[(size_t)v * 16 + c16];
        float2 f0 = __half22float2(*reinterpret_cast<__half2*>(&q.x));
        float2 f1 = __half22float2(*reinterpret_cast<__half2*>(&q.y));
        float2 f2 = __half22float2(*reinterpret_cast<__half2*>(&q.z));
        float2 f3 = __half22float2(*reinterpret_cast<__half2*>(&q.w));
        acc[0] = fmaf(sc, f0.x, acc[0]);
        acc[1] = fmaf(sc, f0.y, acc[1]);
        acc[2] = fmaf(sc, f1.x, acc[2]);
        acc[3] = fmaf(sc, f1.y, acc[3]);
        acc[4] = fmaf(sc, f2.x, acc[4]);
        acc[5] = fmaf(sc, f2.y, acc[5]);
        acc[6] = fmaf(sc, f3.x, acc[6]);
        acc[7] = fmaf(sc, f3.y, acc[7]);
        ssum += sc;
    }
    if (j < end && half == 0) {                    // single tail entry
        int v = g_edge_adj[j];
        float sc = g_inv_sqrt_dv[v];
        uint4 q = X4[(size_t)v * 16 + c16];
        float2 f0 = __half22float2(*reinterpret_cast<__half2*>(&q.x));
        float2 f1 = __half22float2(*reinterpret_cast<__half2*>(&q.y));
        float2 f2 = __half22float2(*reinterpret_cast<__half2*>(&q.z));
        float2 f3 = __half22float2(*reinterpret_cast<__half2*>(&q.w));
        acc[0] = fmaf(sc, f0.x, acc[0]);
        acc[1] = fmaf(sc, f0.y, acc[1]);
        acc[2] = fmaf(sc, f1.x, acc[2]);
        acc[3] = fmaf(sc, f1.y, acc[3]);
        acc[4] = fmaf(sc, f2.x, acc[4]);
        acc[5] = fmaf(sc, f2.y, acc[5]);
        acc[6] = fmaf(sc, f3.x, acc[6]);
        acc[7] = fmaf(sc, f3.y, acc[7]);
        ssum += sc;
    }
    #pragma unroll
    for (int k = 0; k < 8; k++) acc[k] += __shfl_xor_sync(0xFFFFFFFFu, acc[k], 16);
    ssum += __shfl_xor_sync(0xFFFFFFFFu, ssum, 16);
    float s = g_inv_de[gw];
    if (half == 0) {                               // lanes 0-15 write the fp16 row
        __half2 h0 = __floats2half2_rn(acc[0] * s, acc[1] * s);
        __half2 h1 = __floats2half2_rn(acc[2] * s, acc[3] * s);
        __half2 h2 = __floats2half2_rn(acc[4] * s, acc[5] * s);
        __half2 h3 = __floats2half2_rn(acc[6] * s, acc[7] * s);
        uint4 r;
        r.x = *reinterpret_cast<const unsigned*>(&h0);
        r.y = *reinterpret_cast<const unsigned*>(&h1);
        r.z = *reinterpret_cast<const unsigned*>(&h2);
        r.w = *reinterpret_cast<const unsigned*>(&h3);
        ((uint4*)g_Yph)[(size_t)gw * 16 + c16] = r;
        if (lane == 0) g_se[gw] = ssum * s;
    }
}

// ---------------- 5: small GEMM  Ye = Yph @ W + se * b — fp16 in, fp32 math, fp16 out ----------------
#define BM 64
#define XS_STRIDE 132
#define GEMM_SMEM_BYTES ((128 * 128 + BM * XS_STRIDE + 128) * 4)

__global__ void __launch_bounds__(256)
gemm_edges_kernel(const float* __restrict__ W, const float* __restrict__ bias) {
    extern __shared__ float sm[];
    float* Wsm = sm;
    float* Ysm = sm + 128 * 128;
    float* bsm = Ysm + BM * XS_STRIDE;

    cudaTriggerProgrammaticLaunchCompletion();
    int tid = threadIdx.x;
    int row0 = blockIdx.x * BM;

    // prologue: W + bias loads are independent of edge_reduce -> run before sync
    for (int i = tid; i < 128 * 32; i += 256)
        ((float4*)Wsm)[i] = ((const float4*)W)[i];
    if (tid < 32)
        ((float4*)bsm)[tid] = ((const float4*)bias)[tid];

    cudaGridDependencySynchronize();              // now wait for Yph/se

    // stage Yph (fp16) -> Ysm (fp32). 16 uint4 per row; 8 k-values per uint4.
    for (int i = tid; i < BM * 16; i += 256) {
        int m = i >> 4, kq = i & 15;
        int gr = row0 + m;
        uint4 q = (gr < N_EDGES) ? ((const uint4*)g_Yph)[(size_t)gr * 16 + kq]
                                 : make_uint4(0u, 0u, 0u, 0u);
        float2 f0 = __half22float2(*reinterpret_cast<__half2*>(&q.x));
        float2 f1 = __half22float2(*reinterpret_cast<__half2*>(&q.y));
        float2 f2 = __half22float2(*reinterpret_cast<__half2*>(&q.z));
        float2 f3 = __half22float2(*reinterpret_cast<__half2*>(&q.w));
        float* rp = Ysm + m * XS_STRIDE + kq * 8;
        ((float4*)rp)[0] = make_float4(f0.x, f0.y, f1.x, f1.y);
        ((float4*)rp)[1] = make_float4(f2.x, f2.y, f3.x, f3.y);
    }
    __syncthreads();

    int tx = tid & 31;
    int ty = tid >> 5;
    int c0 = tx * 4, r0 = ty * 8;

    float acc[8][4];
    #pragma unroll
    for (int j = 0; j < 8; j++) {
        acc[j][0] = 0.f; acc[j][1] = 0.f; acc[j][2] = 0.f; acc[j][3] = 0.f;
    }

    #pragma unroll 8
    for (int k = 0; k < 128; k++) {
        float4 b4 = *(const float4*)(Wsm + k * 128 + c0);
        #pragma unroll
        for (int j = 0; j < 8; j++) {
            float a = Ysm[(r0 + j) * XS_STRIDE + k];
            acc[j][0] = fmaf(a, b4.x, acc[j][0]);
            acc[j][1] = fmaf(a, b4.y, acc[j][1]);
            acc[j][2] = fmaf(a, b4.z, acc[j][2]);
            acc[j][3] = fmaf(a, b4.w, acc[j][3]);
        }
    }

    float4 bb = *(const float4*)(bsm + c0);
    #pragma unroll
    for (int j = 0; j < 8; j++) {
        int gr = row0 + r0 + j;
        if (gr < N_EDGES) {
            float se = g_se[gr];
            float ox = fmaf(se, bb.x, acc[j][0]);
            float oy = fmaf(se, bb.y, acc[j][1]);
            float oz = fmaf(se, bb.z, acc[j][2]);
            float ow = fmaf(se, bb.w, acc[j][3]);
            __half2 h0 = __floats2half2_rn(ox, oy);
            __half2 h1 = __floats2half2_rn(oz, ow);
            uint2 r;
            r.x = *reinterpret_cast<const unsigned*>(&h0);
            r.y = *reinterpret_cast<const unsigned*>(&h1);
            ((uint2*)g_Yeh)[(size_t)gr * 32 + tx] = r;
        }
    }
}

// ---------------- 6: node gather-reduce — 8-in-flight + 4-in-flight mid-tail + relu ----------------
__global__ void node_reduce_kernel(float* __restrict__ out) {
    int gw = (blockIdx.x * blockDim.x + threadIdx.x) >> 5;
    int lane = threadIdx.x & 31;
    int half = lane >> 4;
    int c16  = lane & 15;
    cudaGridDependencySynchronize();              // wait for Yeh
    if (gw >= N_NODES) return;
    int beg = g_offs_v[gw], end = g_offs_v[gw + 1];
    const uint4* Ye4 = (const uint4*)g_Yeh;        // 16 uint4 per row
    float acc[8] = {0.f, 0.f, 0.f, 0.f, 0.f, 0.f, 0.f, 0.f};
    int j = beg;
    for (; j + 16 <= end; j += 16) {               // 8 rows in flight per group
        int base = j + half * 8;
        int ee[8]; uint4 q[8];
        #pragma unroll
        for (int u = 0; u < 8; u++) ee[u] = g_node_adj[base + u];
        #pragma unroll
        for (int u = 0; u < 8; u++) q[u] = Ye4[(size_t)ee[u] * 16 + c16];
        #pragma unroll
        for (int u = 0; u < 8; u++) {
            float2 f0 = __half22float2(*reinterpret_cast<__half2*>(&q[u].x));
            float2 f1 = __half22float2(*reinterpret_cast<__half2*>(&q[u].y));
            float2 f2 = __half22float2(*reinterpret_cast<__half2*>(&q[u].z));
            float2 f3 = __half22float2(*reinterpret_cast<__half2*>(&q[u].w));
            acc[0] += f0.x; acc[1] += f0.y; acc[2] += f1.x; acc[3] += f1.y;
            acc[4] += f2.x; acc[5] += f2.y; acc[6] += f3.x; acc[7] += f3.y;
        }
    }
    for (; j + 8 <= end; j += 8) {                 // mid tail: 4 rows per group
        int base = j + half * 4;
        int ee[4]; uint4 q[4];
        #pragma unroll
        for (int u = 0; u < 4; u++) ee[u] = g_node_adj[base + u];
        #pragma unroll
        for (int u = 0; u < 4; u++) q[u] = Ye4[(size_t)ee[u] * 16 + c16];
        #pragma unroll
        for (int u = 0; u < 4; u++) {
            float2 f0 = __half22float2(*reinterpret_cast<__half2*>(&q[u].x));
            float2 f1 = __half22float2(*reinterpret_cast<__half2*>(&q[u].y));
            float2 f2 = __half22float2(*reinterpret_cast<__half2*>(&q[u].z));
            float2 f3 = __half22float2(*reinterpret_cast<__half2*>(&q[u].w));
            acc[0] += f0.x; acc[1] += f0.y; acc[2] += f1.x; acc[3] += f1.y;
            acc[4] += f2.x; acc[5] += f2.y; acc[6] += f3.x; acc[7] += f3.y;
        }
    }
    for (; j + 2 <= end; j += 2) {
        int e = g_node_adj[j + half];
        uint4 q = Ye4[(size_t)e * 16 + c16];
        float2 f0 = __half22float2(*reinterpret_cast<__half2*>(&q.x));
        float2 f1 = __half22float2(*reinterpret_cast<__half2*>(&q.y));
        float2 f2 = __half22float2(*reinterpret_cast<__half2*>(&q.z));
        float2 f3 = __half22float2(*reinterpret_cast<__half2*>(&q.w));
        acc[0] += f0.x; acc[1] += f0.y; acc[2] += f1.x; acc[3] += f1.y;
        acc[4] += f2.x; acc[5] += f2.y; acc[6] += f3.x; acc[7] += f3.y;
    }
    if (j < end && half == 0) {
        int e = g_node_adj[j];
        uint4 q = Ye4[(size_t)e * 16 + c16];
        float2 f0 = __half22float2(*reinterpret_cast<__half2*>(&q.x));
        float2 f1 = __half22float2(*reinterpret_cast<__half2*>(&q.y));
        float2 f2 = __half22float2(*reinterpret_cast<__half2*>(&q.z));
        float2 f3 = __half22float2(*reinterpret_cast<__half2*>(&q.w));
        acc[0] += f0.x; acc[1] += f0.y; acc[2] += f1.x; acc[3] += f1.y;
        acc[4] += f2.x; acc[5] += f2.y; acc[6] += f3.x; acc[7] += f3.y;
    }
    #pragma unroll
    for (int k = 0; k < 8; k++) acc[k] += __shfl_xor_sync(0xFFFFFFFFu, acc[k], 16);
    if (half == 0) {
        float s = g_inv_sqrt_dv[gw];
        float* rp = out + (size_t)gw * D + c16 * 8;
        ((float4*)rp)[0] = make_float4(fmaxf(acc[0] * s, 0.f), fmaxf(acc[1] * s, 0.f),
                                       fmaxf(acc[2] * s, 0.f), fmaxf(acc[3] * s, 0.f));
        ((float4*)rp)[1] = make_float4(fmaxf(acc[4] * s, 0.f), fmaxf(acc[5] * s, 0.f),
                                       fmaxf(acc[6] * s, 0.f), fmaxf(acc[7] * s, 0.f));
    }
}

// ---------------- launch: PDL chain with early triggers ----------------
static inline void launch_pdl(void* fn, dim3 grid, dim3 block, size_t smem,
                              void** args) {
    cudaLaunchConfig_t cfg = {};
    cfg.gridDim = grid;
    cfg.blockDim = block;
    cfg.dynamicSmemBytes = smem;
    cfg.stream = 0;
    cudaLaunchAttribute attr[1];
    attr[0].id = cudaLaunchAttributeProgrammaticStreamSerialization;
    attr[0].val.programmaticStreamSerializationAllowed = 1;
    cfg.attrs = attr;
    cfg.numAttrs = 1;
    cudaLaunchKernelExC(&cfg, fn, args);
}

extern "C" void kernel_launch(void* const* d_in, const int* in_sizes, int n_in,
                              void* d_out, int out_size) {
    const float* X     = (const float*)d_in[0];
    const float* W     = (const float*)d_in[1];
    const float* bias  = (const float*)d_in[2];
    const int*   v_idx = (const int*)d_in[3];
    const int*   e_idx = (const int*)d_in[4];
    float* out = (float*)d_out;

    (void)in_sizes; (void)n_in; (void)out_size;

    cudaFuncSetAttribute(gemm_edges_kernel, cudaFuncAttributeMaxDynamicSharedMemorySize,
                         GEMM_SMEM_BYTES);

    degree_kernel<<<(NNZ / 2 + 255) / 256, 256>>>(v_idx, e_idx);

    {   // scan (PDL)
        void* args[] = {};
        launch_pdl((void*)scan_fused_kernel, dim3(NB_V + NB_E), dim3(1024), 0, args);
    }
    {   // fill + convert (PDL; convert prologue overlaps scan, fill waits on offsets)
        void* args[] = {(void*)&X, (void*)&v_idx, (void*)&e_idx};
        launch_pdl((void*)fill_convert_kernel, dim3((N_NODES * 32 + 255) / 256), dim3(256), 0, args);
    }
    {   // edge reduce (PDL)
        void* args[] = {};
        launch_pdl((void*)edge_reduce_kernel, dim3((N_EDGES * 32 + 255) / 256), dim3(256), 0, args);
    }
    {   // gemm (PDL; W-load prologue overlaps edge_reduce tail)
        void* args[] = {(void*)&W, (void*)&bias};
        launch_pdl((void*)gemm_edges_kernel, dim3((N_EDGES + BM - 1) / BM), dim3(256),
                   GEMM_SMEM_BYTES, args);
    }
    {   // node reduce (PDL)
        void* args[] = {(void*)&out};
        launch_pdl((void*)node_reduce_kernel, dim3((N_NODES * 32 + 255) / 256), dim3(256), 0, args);
    }
}

// round 17
// speedup vs baseline: 1.0621x; 1.0024x over previous
#include <cuda_runtime.h>
#include <cuda_fp16.h>
#include <math.h>

#define N_NODES 100000
#define N_EDGES 20000
#define NNZ     1600000
#define D       128
#define NB_V    ((N_NODES + 1023) / 1024)   // 98
#define NB_E    ((N_EDGES + 1023) / 1024)   // 20

// ---------------- scratch (device globals: allocation-free rule) ----------------
// Invariant: g_cnt_v/g_cnt_e/g_state_v/g_state_e are ZERO at entry (statically
// zero-initialized; re-zeroed by fill_convert_kernel after last use each execution).
__device__ int   g_cnt_v[N_NODES];
__device__ int   g_cnt_e[N_EDGES];
__device__ unsigned long long g_state_v[NB_V];    // lookback: (value<<2)|flag
__device__ unsigned long long g_state_e[NB_E];
__device__ int   g_offs_v[N_NODES + 1];
__device__ int   g_offs_e[N_EDGES + 1];
__device__ int   g_pos[NNZ];                      // (pos_v << 16) | pos_e
__device__ float g_inv_sqrt_dv[N_NODES];
__device__ float g_inv_de[N_EDGES];
__device__ int   g_edge_adj[NNZ];                 // per-edge list of vertex ids
__device__ unsigned short g_node_adj[NNZ];        // per-node list of edge ids (<2^16)
__device__ unsigned g_Xh[(size_t)N_NODES * 64];   // X in half2 bit patterns
__device__ unsigned g_Yph[(size_t)N_EDGES * 64];  // Yp in half2 (edge aggregates)
__device__ float g_se[N_EDGES];                   // inv_de * H^T Dv^-1/2 1
__device__ unsigned g_Yeh[(size_t)N_EDGES * 64];  // Ye in half2

// ---------------- 1: degree histograms + packed rank capture (4 entries/thread) ----------------
__global__ void degree_kernel(const int* __restrict__ v_idx,
                              const int* __restrict__ e_idx) {
    cudaTriggerProgrammaticLaunchCompletion();       // successors see counts via scan's sync
    int t = blockIdx.x * blockDim.x + threadIdx.x;   // covers NNZ/4 (NNZ % 4 == 0)
    if (t < NNZ / 4) {
        int4 vv = ((const int4*)v_idx)[t];
        int4 ee = ((const int4*)e_idx)[t];
        int pv0 = atomicAdd(&g_cnt_v[vv.x], 1);
        int pe0 = atomicAdd(&g_cnt_e[ee.x], 1);
        int pv1 = atomicAdd(&g_cnt_v[vv.y], 1);
        int pe1 = atomicAdd(&g_cnt_e[ee.y], 1);
        int pv2 = atomicAdd(&g_cnt_v[vv.z], 1);
        int pe2 = atomicAdd(&g_cnt_e[ee.z], 1);
        int pv3 = atomicAdd(&g_cnt_v[vv.w], 1);
        int pe3 = atomicAdd(&g_cnt_e[ee.w], 1);
        ((int4*)g_pos)[t] = make_int4((pv0 << 16) | pe0, (pv1 << 16) | pe1,
                                      (pv2 << 16) | pe2, (pv3 << 16) | pe3);
    }
}

// ---------------- 2: single-pass decoupled-lookback scan (both arrays) + inv factors ----------------
// Trigger is AFTER the sync: guarantees fill_convert launches only once degree
// has fully completed -> fill's pre-sync g_pos/v/e loads are safe.
__global__ void scan_fused_kernel() {
    __shared__ int wsum[32];
    __shared__ int s_agg;
    __shared__ int s_prefix;
    int tid = threadIdx.x;                        // 1024
    int b = blockIdx.x;
    int chain_e = (b >= NB_V);
    int pb = chain_e ? (b - NB_V) : b;
    const int* in   = chain_e ? g_cnt_e : g_cnt_v;
    int*       out  = chain_e ? g_offs_e : g_offs_v;
    int        n    = chain_e ? N_EDGES : N_NODES;
    unsigned long long* st = chain_e ? g_state_e : g_state_v;

    int i = pb * 1024 + tid;

    cudaGridDependencySynchronize();              // wait for degree counts
    cudaTriggerProgrammaticLaunchCompletion();    // degree complete -> fill may launch

    int x = (i < n) ? in[i] : 0;

    if (i < n) {
        if (chain_e) g_inv_de[i] = (x > 0) ? (1.0f / (float)x) : 0.0f;
        else         g_inv_sqrt_dv[i] = (x > 0) ? rsqrtf((float)x) : 0.0f;
    }

    int v = x;
    #pragma unroll
    for (int o = 1; o < 32; o <<= 1) {
        int t = __shfl_up_sync(0xFFFFFFFFu, v, o);
        if ((tid & 31) >= o) v += t;
    }
    if ((tid & 31) == 31) wsum[tid >> 5] = v;
    __syncthreads();
    if (tid < 32) {
        int w = wsum[tid];
        #pragma unroll
        for (int o = 1; o < 32; o <<= 1) {
            int t = __shfl_up_sync(0xFFFFFFFFu, w, o);
            if (tid >= o) w += t;
        }
        wsum[tid] = w;
    }
    __syncthreads();
    int warppre = (tid >= 32) ? wsum[(tid >> 5) - 1] : 0;
    int incl = v + warppre;
    if (tid == 1023) s_agg = incl;
    __syncthreads();

    if (tid < 32) {
        int agg = s_agg;
        int run = 0;
        if (pb == 0) {
            if (tid == 0) atomicExch(&st[0], ((unsigned long long)agg << 2) | 2ULL);
        } else {
            if (tid == 0) atomicExch(&st[pb], ((unsigned long long)agg << 2) | 1ULL);
            __syncwarp();
            int p = pb - 1;
            while (true) {
                int idx = p - (int)tid;
                int flag;
                int val = 0;
                if (idx >= 0) {
                    unsigned long long s;
                    do { s = atomicAdd(&st[idx], 0ULL); flag = (int)(s & 3ULL); } while (flag == 0);
                    val = (int)(s >> 2);
                } else {
                    flag = 2;
                }
                unsigned m2 = __ballot_sync(0xFFFFFFFFu, flag == 2);
                int k = __ffs(m2) - 1;
                int contrib = (m2 == 0u || (int)tid <= k) ? val : 0;
                #pragma unroll
                for (int o = 16; o; o >>= 1) contrib += __shfl_down_sync(0xFFFFFFFFu, contrib, o);
                contrib = __shfl_sync(0xFFFFFFFFu, contrib, 0);
                run += contrib;
                if (m2) break;
                p -= 32;
            }
            if (tid == 0) atomicExch(&st[pb], ((unsigned long long)(agg + run) << 2) | 2ULL);
        }
        if (tid == 0) s_prefix = run;
    }
    __syncthreads();

    if (i < n) out[i] = s_prefix + incl - x;
    if (b == 0 && tid == 0) {
        g_offs_v[N_NODES] = NNZ;
        g_offs_e[N_EDGES] = NNZ;
    }
}

// ---------------- 3: CSR fill + X->half2 convert; index loads hoisted pre-sync ----------------
__global__ void fill_convert_kernel(const float* __restrict__ X,
                                    const int* __restrict__ v_idx,
                                    const int* __restrict__ e_idx) {
    cudaTriggerProgrammaticLaunchCompletion();    // edge_reduce may launch early
    int i = blockIdx.x * blockDim.x + threadIdx.x;   // grid covers N_NODES*32
    // pre-sync work: inputs + degree-written g_pos (degree proven complete by
    // scan's post-sync trigger); only the offs-dependent scatter must wait.
    if (i < N_NODES * 32) {
        float4 p = __ldcs(((const float4*)X) + i);   // evict-first: X read once
        __half2 a = __floats2half2_rn(p.x, p.y);
        __half2 b = __floats2half2_rn(p.z, p.w);
        uint2 r;
        r.x = *reinterpret_cast<const unsigned*>(&a);
        r.y = *reinterpret_cast<const unsigned*>(&b);
        ((uint2*)g_Xh)[i] = r;
    }
    int v = 0, e = 0, p = 0;
    if (i < NNZ) {
        v = v_idx[i];
        e = e_idx[i];
        p = g_pos[i];
    }
    cudaGridDependencySynchronize();              // wait for offsets (scan)
    if (i < NNZ) {
        g_edge_adj[g_offs_e[e] + (p & 0xFFFF)] = v;
        g_node_adj[g_offs_v[v] + (p >> 16)] = (unsigned short)e;
    }
    if (i < N_NODES) g_cnt_v[i] = 0;
    if (i < N_EDGES) g_cnt_e[i] = 0;
    if (i < NB_V) g_state_v[i] = 0ULL;
    if (i < NB_E) g_state_e[i] = 0ULL;
}

// ---------------- 4: edge gather-reduce — LDG.128, 8 rows in flight per group, fp16 out ----------------
__global__ void edge_reduce_kernel() {
    cudaTriggerProgrammaticLaunchCompletion();    // gemm may launch early (W prologue)
    int gw = (blockIdx.x * blockDim.x + threadIdx.x) >> 5;
    int lane = threadIdx.x & 31;
    int half = lane >> 4;
    int c16  = lane & 15;
    cudaGridDependencySynchronize();              // wait for edge_adj + Xh
    if (gw >= N_EDGES) return;
    int beg = g_offs_e[gw], end = g_offs_e[gw + 1];
    const uint4* X4 = (const uint4*)g_Xh;          // 16 uint4 per row
    float acc[8] = {0.f, 0.f, 0.f, 0.f, 0.f, 0.f, 0.f, 0.f};
    float ssum = 0.f;
    int j = beg;
    for (; j + 16 <= end; j += 16) {               // 8 rows in flight per group
        int base = j + half * 8;
        int vv[8]; float sc[8]; uint4 q[8];
        #pragma unroll
        for (int u = 0; u < 8; u++) vv[u] = g_edge_adj[base + u];
        #pragma unroll
        for (int u = 0; u < 8; u++) sc[u] = g_inv_sqrt_dv[vv[u]];
        #pragma unroll
        for (int u = 0; u < 8; u++) q[u] = X4[(size_t)vv[u] * 16 + c16];
        #pragma unroll
        for (int u = 0; u < 8; u++) {
            float2 f0 = __half22float2(*reinterpret_cast<__half2*>(&q[u].x));
            float2 f1 = __half22float2(*reinterpret_cast<__half2*>(&q[u].y));
            float2 f2 = __half22float2(*reinterpret_cast<__half2*>(&q[u].z));
            float2 f3 = __half22float2(*reinterpret_cast<__half2*>(&q[u].w));
            acc[0] = fmaf(sc[u], f0.x, acc[0]);
            acc[1] = fmaf(sc[u], f0.y, acc[1]);
            acc[2] = fmaf(sc[u], f1.x, acc[2]);
            acc[3] = fmaf(sc[u], f1.y, acc[3]);
            acc[4] = fmaf(sc[u], f2.x, acc[4]);
            acc[5] = fmaf(sc[u], f2.y, acc[5]);
            acc[6] = fmaf(sc[u], f3.x, acc[6]);
            acc[7] = fmaf(sc[u], f3.y, acc[7]);
            ssum += sc[u];
        }
    }
    for (; j + 8 <= end; j += 8) {                 // mid tail: 4 rows per group
        int base = j + half * 4;
        int vv[4]; float sc[4]; uint4 q[4];
        #pragma unroll
        for (int u = 0; u < 4; u++) vv[u] = g_edge_adj[base + u];
        #pragma unroll
        for (int u = 0; u < 4; u++) sc[u] = g_inv_sqrt_dv[vv[u]];
        #pragma unroll
        for (int u = 0; u < 4; u++) q[u] = X4[(size_t)vv[u] * 16 + c16];
        #pragma unroll
        for (int u = 0; u < 4; u++) {
            float2 f0 = __half22float2(*reinterpret_cast<__half2*>(&q[u].x));
            float2 f1 = __half22float2(*reinterpret_cast<__half2*>(&q[u].y));
            float2 f2 = __half22float2(*reinterpret_cast<__half2*>(&q[u].z));
            float2 f3 = __half22float2(*reinterpret_cast<__half2*>(&q[u].w));
            acc[0] = fmaf(sc[u], f0.x, acc[0]);
            acc[1] = fmaf(sc[u], f0.y, acc[1]);
            acc[2] = fmaf(sc[u], f1.x, acc[2]);
            acc[3] = fmaf(sc[u], f1.y, acc[3]);
            acc[4] = fmaf(sc[u], f2.x, acc[4]);
            acc[5] = fmaf(sc[u], f2.y, acc[5]);
            acc[6] = fmaf(sc[u], f3.x, acc[6]);
            acc[7] = fmaf(sc[u], f3.y, acc[7]);
            ssum += sc[u];
        }
    }
    for (; j + 2 <= end; j += 2) {                 // pair tail
        int v = g_edge_adj[j + half];
        float sc = g_inv_sqrt_dv[v];
        uint4 q = X4[(size_t)v * 16 + c16];
        float2 f0 = __half22float2(*reinterpret_cast<__half2*>(&q.x));
        float2 f1 = __half22float2(*reinterpret_cast<__half2*>(&q.y));
        float2 f2 = __half22float2(*reinterpret_cast<__half2*>(&q.z));
        float2 f3 = __half22float2(*reinterpret_cast<__half2*>(&q.w));
        acc[0] = fmaf(sc, f0.x, acc[0]);
        acc[1] = fmaf(sc, f0.y, acc[1]);
        acc[2] = fmaf(sc, f1.x, acc[2]);
        acc[3] = fmaf(sc, f1.y, acc[3]);
        acc[4] = fmaf(sc, f2.x, acc[4]);
        acc[5] = fmaf(sc, f2.y, acc[5]);
        acc[6] = fmaf(sc, f3.x, acc[6]);
        acc[7] = fmaf(sc, f3.y, acc[7]);
        ssum += sc;
    }
    if (j < end && half == 0) {                    // single tail entry
        int v = g_edge_adj[j];
        float sc = g_inv_sqrt_dv[v];
        uint4 q = X4[(size_t)v * 16 + c16];
        float2 f0 = __half22float2(*reinterpret_cast<__half2*>(&q.x));
        float2 f1 = __half22float2(*reinterpret_cast<__half2*>(&q.y));
        float2 f2 = __half22float2(*reinterpret_cast<__half2*>(&q.z));
        float2 f3 = __half22float2(*reinterpret_cast<__half2*>(&q.w));
        acc[0] = fmaf(sc, f0.x, acc[0]);
        acc[1] = fmaf(sc, f0.y, acc[1]);
        acc[2] = fmaf(sc, f1.x, acc[2]);
        acc[3] = fmaf(sc, f1.y, acc[3]);
        acc[4] = fmaf(sc, f2.x, acc[4]);
        acc[5] = fmaf(sc, f2.y, acc[5]);
        acc[6] = fmaf(sc, f3.x, acc[6]);
        acc[7] = fmaf(sc, f3.y, acc[7]);
        ssum += sc;
    }
    #pragma unroll
    for (int k = 0; k < 8; k++) acc[k] += __shfl_xor_sync(0xFFFFFFFFu, acc[k], 16);
    ssum += __shfl_xor_sync(0xFFFFFFFFu, ssum, 16);
    float s = g_inv_de[gw];
    if (half == 0) {                               // lanes 0-15 write the fp16 row
        __half2 h0 = __floats2half2_rn(acc[0] * s, acc[1] * s);
        __half2 h1 = __floats2half2_rn(acc[2] * s, acc[3] * s);
        __half2 h2 = __floats2half2_rn(acc[4] * s, acc[5] * s);
        __half2 h3 = __floats2half2_rn(acc[6] * s, acc[7] * s);
        uint4 r;
        r.x = *reinterpret_cast<const unsigned*>(&h0);
        r.y = *reinterpret_cast<const unsigned*>(&h1);
        r.z = *reinterpret_cast<const unsigned*>(&h2);
        r.w = *reinterpret_cast<const unsigned*>(&h3);
        ((uint4*)g_Yph)[(size_t)gw * 16 + c16] = r;
        if (lane == 0) g_se[gw] = ssum * s;
    }
}

// ---------------- 5: small GEMM  Ye = Yph @ W + se * b — fp16 in, fp32 math, fp16 out ----------------
// Trigger AFTER the sync: guarantees node_reduce launches only once edge_reduce
// (and transitively fill+scan) completed -> node_reduce's pre-sync loads are safe.
#define BM 64
#define XS_STRIDE 132
#define GEMM_SMEM_BYTES ((128 * 128 + BM * XS_STRIDE + 128) * 4)

__global__ void __launch_bounds__(256)
gemm_edges_kernel(const float* __restrict__ W, const float* __restrict__ bias) {
    extern __shared__ float sm[];
    float* Wsm = sm;
    float* Ysm = sm + 128 * 128;
    float* bsm = Ysm + BM * XS_STRIDE;

    int tid = threadIdx.x;
    int row0 = blockIdx.x * BM;

    // prologue: W + bias loads are independent of edge_reduce -> run before sync
    for (int i = tid; i < 128 * 32; i += 256)
        ((float4*)Wsm)[i] = ((const float4*)W)[i];
    if (tid < 32)
        ((float4*)bsm)[tid] = ((const float4*)bias)[tid];

    cudaGridDependencySynchronize();              // now wait for Yph/se
    cudaTriggerProgrammaticLaunchCompletion();    // edge_reduce complete -> node_reduce may launch

    // stage Yph (fp16) -> Ysm (fp32). 16 uint4 per row; 8 k-values per uint4.
    for (int i = tid; i < BM * 16; i += 256) {
        int m = i >> 4, kq = i & 15;
        int gr = row0 + m;
        uint4 q = (gr < N_EDGES) ? ((const uint4*)g_Yph)[(size_t)gr * 16 + kq]
                                 : make_uint4(0u, 0u, 0u, 0u);
        float2 f0 = __half22float2(*reinterpret_cast<__half2*>(&q.x));
        float2 f1 = __half22float2(*reinterpret_cast<__half2*>(&q.y));
        float2 f2 = __half22float2(*reinterpret_cast<__half2*>(&q.z));
        float2 f3 = __half22float2(*reinterpret_cast<__half2*>(&q.w));
        float* rp = Ysm + m * XS_STRIDE + kq * 8;
        ((float4*)rp)[0] = make_float4(f0.x, f0.y, f1.x, f1.y);
        ((float4*)rp)[1] = make_float4(f2.x, f2.y, f3.x, f3.y);
    }
    __syncthreads();

    int tx = tid & 31;
    int ty = tid >> 5;
    int c0 = tx * 4, r0 = ty * 8;

    float acc[8][4];
    #pragma unroll
    for (int j = 0; j < 8; j++) {
        acc[j][0] = 0.f; acc[j][1] = 0.f; acc[j][2] = 0.f; acc[j][3] = 0.f;
    }

    #pragma unroll 8
    for (int k = 0; k < 128; k++) {
        float4 b4 = *(const float4*)(Wsm + k * 128 + c0);
        #pragma unroll
        for (int j = 0; j < 8; j++) {
            float a = Ysm[(r0 + j) * XS_STRIDE + k];
            acc[j][0] = fmaf(a, b4.x, acc[j][0]);
            acc[j][1] = fmaf(a, b4.y, acc[j][1]);
            acc[j][2] = fmaf(a, b4.z, acc[j][2]);
            acc[j][3] = fmaf(a, b4.w, acc[j][3]);
        }
    }

    float4 bb = *(const float4*)(bsm + c0);
    #pragma unroll
    for (int j = 0; j < 8; j++) {
        int gr = row0 + r0 + j;
        if (gr < N_EDGES) {
            float se = g_se[gr];
            float ox = fmaf(se, bb.x, acc[j][0]);
            float oy = fmaf(se, bb.y, acc[j][1]);
            float oz = fmaf(se, bb.z, acc[j][2]);
            float ow = fmaf(se, bb.w, acc[j][3]);
            __half2 h0 = __floats2half2_rn(ox, oy);
            __half2 h1 = __floats2half2_rn(oz, ow);
            uint2 r;
            r.x = *reinterpret_cast<const unsigned*>(&h0);
            r.y = *reinterpret_cast<const unsigned*>(&h1);
            ((uint2*)g_Yeh)[(size_t)gr * 32 + tx] = r;
        }
    }
}

// ---------------- 6: node gather-reduce — offsets/scale hoisted pre-sync + relu ----------------
__global__ void node_reduce_kernel(float* __restrict__ out) {
    int gw = (blockIdx.x * blockDim.x + threadIdx.x) >> 5;
    int lane = threadIdx.x & 31;
    int half = lane >> 4;
    int c16  = lane & 15;
    // pre-sync: offs_v/inv_sqrt_dv (scan) and node_adj (fill) are complete —
    // gemm's post-sync trigger proves edge_reduce (hence fill & scan) finished.
    int beg = 0, end = 0;
    float s = 0.f;
    if (gw < N_NODES) {
        beg = g_offs_v[gw];
        end = g_offs_v[gw + 1];
        s   = g_inv_sqrt_dv[gw];
    }
    cudaGridDependencySynchronize();              // wait for Yeh (gemm)
    if (gw >= N_NODES) return;
    const uint4* Ye4 = (const uint4*)g_Yeh;        // 16 uint4 per row
    float acc[8] = {0.f, 0.f, 0.f, 0.f, 0.f, 0.f, 0.f, 0.f};
    int j = beg;
    for (; j + 16 <= end; j += 16) {               // 8 rows in flight per group
        int base = j + half * 8;
        int ee[8]; uint4 q[8];
        #pragma unroll
        for (int u = 0; u < 8; u++) ee[u] = g_node_adj[base + u];
        #pragma unroll
        for (int u = 0; u < 8; u++) q[u] = Ye4[(size_t)ee[u] * 16 + c16];
        #pragma unroll
        for (int u = 0; u < 8; u++) {
            float2 f0 = __half22float2(*reinterpret_cast<__half2*>(&q[u].x));
            float2 f1 = __half22float2(*reinterpret_cast<__half2*>(&q[u].y));
            float2 f2 = __half22float2(*reinterpret_cast<__half2*>(&q[u].z));
            float2 f3 = __half22float2(*reinterpret_cast<__half2*>(&q[u].w));
            acc[0] += f0.x; acc[1] += f0.y; acc[2] += f1.x; acc[3] += f1.y;
            acc[4] += f2.x; acc[5] += f2.y; acc[6] += f3.x; acc[7] += f3.y;
        }
    }
    for (; j + 8 <= end; j += 8) {                 // mid tail: 4 rows per group
        int base = j + half * 4;
        int ee[4]; uint4 q[4];
        #pragma unroll
        for (int u = 0; u < 4; u++) ee[u] = g_node_adj[base + u];
        #pragma unroll
        for (int u = 0; u < 4; u++) q[u] = Ye4[(size_t)ee[u] * 16 + c16];
        #pragma unroll
        for (int u = 0; u < 4; u++) {
            float2 f0 = __half22float2(*reinterpret_cast<__half2*>(&q[u].x));
            float2 f1 = __half22float2(*reinterpret_cast<__half2*>(&q[u].y));
            float2 f2 = __half22float2(*reinterpret_cast<__half2*>(&q[u].z));
            float2 f3 = __half22float2(*reinterpret_cast<__half2*>(&q[u].w));
            acc[0] += f0.x; acc[1] += f0.y; acc[2] += f1.x; acc[3] += f1.y;
            acc[4] += f2.x; acc[5] += f2.y; acc[6] += f3.x; acc[7] += f3.y;
        }
    }
    for (; j + 2 <= end; j += 2) {
        int e = g_node_adj[j + half];
        uint4 q = Ye4[(size_t)e * 16 + c16];
        float2 f0 = __half22float2(*reinterpret_cast<__half2*>(&q.x));
        float2 f1 = __half22float2(*reinterpret_cast<__half2*>(&q.y));
        float2 f2 = __half22float2(*reinterpret_cast<__half2*>(&q.z));
        float2 f3 = __half22float2(*reinterpret_cast<__half2*>(&q.w));
        acc[0] += f0.x; acc[1] += f0.y; acc[2] += f1.x; acc[3] += f1.y;
        acc[4] += f2.x; acc[5] += f2.y; acc[6] += f3.x; acc[7] += f3.y;
    }
    if (j < end && half == 0) {
        int e = g_node_adj[j];
        uint4 q = Ye4[(size_t)e * 16 + c16];
        float2 f0 = __half22float2(*reinterpret_cast<__half2*>(&q.x));
        float2 f1 = __half22float2(*reinterpret_cast<__half2*>(&q.y));
        float2 f2 = __half22float2(*reinterpret_cast<__half2*>(&q.z));
        float2 f3 = __half22float2(*reinterpret_cast<__half2*>(&q.w));
        acc[0] += f0.x; acc[1] += f0.y; acc[2] += f1.x; acc[3] += f1.y;
        acc[4] += f2.x; acc[5] += f2.y; acc[6] += f3.x; acc[7] += f3.y;
    }
    #pragma unroll
    for (int k = 0; k < 8; k++) acc[k] += __shfl_xor_sync(0xFFFFFFFFu, acc[k], 16);
    if (half == 0) {
        float* rp = out + (size_t)gw * D + c16 * 8;
        ((float4*)rp)[0] = make_float4(fmaxf(acc[0] * s, 0.f), fmaxf(acc[1] * s, 0.f),
                                       fmaxf(acc[2] * s, 0.f), fmaxf(acc[3] * s, 0.f));
        ((float4*)rp)[1] = make_float4(fmaxf(acc[4] * s, 0.f), fmaxf(acc[5] * s, 0.f),
                                       fmaxf(acc[6] * s, 0.f), fmaxf(acc[7] * s, 0.f));
    }
}

// ---------------- launch: PDL chain with visibility-proving trigger placement ----------------
static inline void launch_pdl(void* fn, dim3 grid, dim3 block, size_t smem,
                              void** args) {
    cudaLaunchConfig_t cfg = {};
    cfg.gridDim = grid;
    cfg.blockDim = block;
    cfg.dynamicSmemBytes = smem;
    cfg.stream = 0;
    cudaLaunchAttribute attr[1];
    attr[0].id = cudaLaunchAttributeProgrammaticStreamSerialization;
    attr[0].val.programmaticStreamSerializationAllowed = 1;
    cfg.attrs = attr;
    cfg.numAttrs = 1;
    cudaLaunchKernelExC(&cfg, fn, args);
}

extern "C" void kernel_launch(void* const* d_in, const int* in_sizes, int n_in,
                              void* d_out, int out_size) {
    const float* X     = (const float*)d_in[0];
    const float* W     = (const float*)d_in[1];
    const float* bias  = (const float*)d_in[2];
    const int*   v_idx = (const int*)d_in[3];
    const int*   e_idx = (const int*)d_in[4];
    float* out = (float*)d_out;

    (void)in_sizes; (void)n_in; (void)out_size;

    cudaFuncSetAttribute(gemm_edges_kernel, cudaFuncAttributeMaxDynamicSharedMemorySize,
                         GEMM_SMEM_BYTES);

    degree_kernel<<<(NNZ / 4 + 255) / 256, 256>>>(v_idx, e_idx);

    {   // scan (PDL)
        void* args[] = {};
        launch_pdl((void*)scan_fused_kernel, dim3(NB_V + NB_E), dim3(1024), 0, args);
    }
    {   // fill + convert (PDL; convert + index loads overlap scan)
        void* args[] = {(void*)&X, (void*)&v_idx, (void*)&e_idx};
        launch_pdl((void*)fill_convert_kernel, dim3((N_NODES * 32 + 255) / 256), dim3(256), 0, args);
    }
    {   // edge reduce (PDL)
        void* args[] = {};
        launch_pdl((void*)edge_reduce_kernel, dim3((N_EDGES * 32 + 255) / 256), dim3(256), 0, args);
    }
    {   // gemm (PDL; W-load prologue overlaps edge_reduce tail)
        void* args[] = {(void*)&W, (void*)&bias};
        launch_pdl((void*)gemm_edges_kernel, dim3((N_EDGES + BM - 1) / BM), dim3(256),
                   GEMM_SMEM_BYTES, args);
    }
    {   // node reduce (PDL; offs/scale loads overlap gemm)
        void* args[] = {(void*)&out};
        launch_pdl((void*)node_reduce_kernel, dim3((N_NODES * 32 + 255) / 256), dim3(256), 0, args);
    }
}